// round 3
// baseline (speedup 1.0000x reference)
#include <cuda_runtime.h>

#define NODES  50000
#define NEDGE  800000
#define AUGE   (NEDGE + NODES)     // 850000
#define INC    128
#define HIDC   64
#define NHEADS 4
#define H1DIM  (NHEADS * HIDC)     // 256

typedef unsigned long long u64;

// ------------------------- scratch (static device memory) -------------------
__device__ float    g_h1lin[(size_t)NODES * H1DIM];
__device__ float    g_agg1 [(size_t)NODES * H1DIM];
__device__ float    g_h2lin[(size_t)NODES * HIDC];
__device__ float    g_agg2 [(size_t)NODES * HIDC];
__device__ float    g_PQ   [(size_t)NODES * 2 * HIDC];
__device__ float    g_Bc   [HIDC * 2 * HIDC];
__device__ float    g_ssrc1[NODES * NHEADS];
__device__ float    g_sdst1[NODES * NHEADS];
__device__ float    g_den1 [NODES * NHEADS];
__device__ float    g_ex1  [(size_t)AUGE * NHEADS];
__device__ float    g_ssrc2[NODES];
__device__ float    g_sdst2[NODES];
__device__ float    g_den2 [NODES];
__device__ float    g_ex2  [AUGE];
__device__ int      g_ei   [2 * NEDGE];
__device__ int      g_is64;

// ------------------------- helpers ------------------------------------------
__device__ __forceinline__ void redAdd4(float4* p, float4 v) {
    asm volatile("red.global.add.v4.f32 [%0], {%1,%2,%3,%4};"
                 :: "l"(p), "f"(v.x), "f"(v.y), "f"(v.z), "f"(v.w) : "memory");
}
__device__ __forceinline__ float lrelu(float x) { return x >= 0.f ? x : 0.2f * x; }
__device__ __forceinline__ void ffma2(u64& d, u64 a, u64 b) {
    asm("fma.rn.f32x2 %0, %1, %2, %0;" : "+l"(d) : "l"(a), "l"(b));
}
__device__ __forceinline__ float2 unpk(u64 v) {
    float2 r; asm("mov.b64 {%0,%1}, %2;" : "=f"(r.x), "=f"(r.y) : "l"(v)); return r;
}

// ------------------------- edge index dtype detect + normalize --------------
__global__ void detect_k(const void* p) {
    __shared__ int nz;
    if (threadIdx.x == 0) nz = 0;
    __syncthreads();
    const int2* q = (const int2*)p;
    for (int i = threadIdx.x; i < 4096; i += blockDim.x)
        if (q[i].y != 0) nz = 1;
    __syncthreads();
    if (threadIdx.x == 0) g_is64 = (nz == 0) ? 1 : 0;
}
__global__ void conv_k(const void* p) {
    int i = blockIdx.x * blockDim.x + threadIdx.x;
    if (i >= 2 * NEDGE) return;
    long long v = g_is64 ? ((const long long*)p)[i]
                         : (long long)((const int*)p)[i];
    g_ei[i] = (int)v;
}

// ------------------------- fused init + Wm1 repack --------------------------
__global__ void setup_k(const float* __restrict__ Wm1) {
    long i = (long)blockIdx.x * blockDim.x + threadIdx.x;
    if (i < (long)NODES * H1DIM) g_agg1[i] = 0.f;
    if (i < (long)NODES * HIDC)  g_agg2[i] = 0.f;
    if (i < NODES * NHEADS)      g_den1[i] = 0.f;
    if (i < NODES)               g_den2[i] = 0.f;
    if (i < HIDC * 2 * HIDC) {
        int k = (int)(i >> 7), j = (int)(i & 127);
        g_Bc[i] = (j < HIDC) ? Wm1[k * HIDC + j] : Wm1[(HIDC + k) * HIDC + (j - HIDC)];
    }
}

// ------------------------- f32x2 GEMM: 64x64 tile, Kt=32, 4x4/thread --------
// AMODE: 0 = plain A, 1 = relu(A + biasA[k]), 2 = A + biasA[k]
template<int AMODE>
__global__ void __launch_bounds__(256) gemm32_k(
    const float* __restrict__ A, const float* __restrict__ B,
    const float* __restrict__ biasA, float* __restrict__ C,
    int M, int K, int Nc)
{
    __shared__ float At[32][68];        // [k][m]   (transposed A)
    __shared__ float Bd[2][32][68];     // [plane][k][dup pairs]: plane0 = cols 4tc+0,1
    int t = threadIdx.x;
    int m0 = blockIdx.x * 64, n0 = blockIdx.y * 64;
    int tr = t >> 4, tc = t & 15;
    u64 acc[2][4] = {};
    for (int kt = 0; kt < K; kt += 32) {
        // A: 64 rows x 32 k, transposed into At[k][m]
        #pragma unroll
        for (int i = t; i < 512; i += 256) {
            int r = i >> 3, kq = (i & 7) << 2;
            int gr = m0 + r;
            float4 v = make_float4(0.f, 0.f, 0.f, 0.f);
            if (gr < M) v = *(const float4*)(A + (long)gr * K + kt + kq);
            if (AMODE) {
                float4 b = *(const float4*)(biasA + kt + kq);
                v.x += b.x; v.y += b.y; v.z += b.z; v.w += b.w;
                if (AMODE == 1) {
                    v.x = fmaxf(v.x, 0.f); v.y = fmaxf(v.y, 0.f);
                    v.z = fmaxf(v.z, 0.f); v.w = fmaxf(v.w, 0.f);
                }
            }
            At[kq + 0][r] = v.x; At[kq + 1][r] = v.y;
            At[kq + 2][r] = v.z; At[kq + 3][r] = v.w;
        }
        // B: 32 k x 64 n, duplicated pairs split into 2 planes
        #pragma unroll
        for (int i = t; i < 512; i += 256) {
            int kr = i >> 4, c4 = (i & 15) << 2;
            float4 v = *(const float4*)(B + (long)(kt + kr) * Nc + n0 + c4);
            *(float4*)&Bd[0][kr][c4] = make_float4(v.x, v.x, v.y, v.y);
            *(float4*)&Bd[1][kr][c4] = make_float4(v.z, v.z, v.w, v.w);
        }
        __syncthreads();
        #pragma unroll
        for (int kk = 0; kk < 32; kk++) {
            u64 a01, a23, b00, b01, b10, b11;
            { ulonglong2 av = *(const ulonglong2*)&At[kk][tr * 4];     a01 = av.x; a23 = av.y; }
            { ulonglong2 bv = *(const ulonglong2*)&Bd[0][kk][tc * 4];  b00 = bv.x; b01 = bv.y; }
            { ulonglong2 bv = *(const ulonglong2*)&Bd[1][kk][tc * 4];  b10 = bv.x; b11 = bv.y; }
            ffma2(acc[0][0], a01, b00); ffma2(acc[1][0], a23, b00);
            ffma2(acc[0][1], a01, b01); ffma2(acc[1][1], a23, b01);
            ffma2(acc[0][2], a01, b10); ffma2(acc[1][2], a23, b10);
            ffma2(acc[0][3], a01, b11); ffma2(acc[1][3], a23, b11);
        }
        __syncthreads();
    }
    // acc[mp][n]: pair = rows (tr*4+2mp, tr*4+2mp+1), col = tc*4+n
    #pragma unroll
    for (int mp = 0; mp < 2; mp++) {
        float2 c0 = unpk(acc[mp][0]), c1 = unpk(acc[mp][1]);
        float2 c2 = unpk(acc[mp][2]), c3 = unpk(acc[mp][3]);
        int r0 = m0 + tr * 4 + mp * 2;
        if (r0 < M)
            *(float4*)(C + (long)r0 * Nc + n0 + tc * 4) =
                make_float4(c0.x, c1.x, c2.x, c3.x);
        if (r0 + 1 < M)
            *(float4*)(C + (long)(r0 + 1) * Nc + n0 + tc * 4) =
                make_float4(c0.y, c1.y, c2.y, c3.y);
    }
}

// ------------------------- layer-1 scores: warp per node, 4 heads -----------
__global__ void scores1_k(const float* __restrict__ h,
                          const float* __restrict__ asrc,
                          const float* __restrict__ adst,
                          float* __restrict__ ssrc, float* __restrict__ sdst)
{
    int w = (int)(((long)blockIdx.x * blockDim.x + threadIdx.x) >> 5);
    if (w >= NODES) return;
    int lane = threadIdx.x & 31;
    const float4* row = (const float4*)(h + (long)w * 256);
    float4 v0 = row[lane * 2], v1 = row[lane * 2 + 1];
    const float4* pa = (const float4*)asrc;
    const float4* pd = (const float4*)adst;
    float4 a0 = pa[lane * 2], a1 = pa[lane * 2 + 1];
    float4 d0 = pd[lane * 2], d1 = pd[lane * 2 + 1];
    float ss = v0.x*a0.x + v0.y*a0.y + v0.z*a0.z + v0.w*a0.w
             + v1.x*a1.x + v1.y*a1.y + v1.z*a1.z + v1.w*a1.w;
    float sd = v0.x*d0.x + v0.y*d0.y + v0.z*d0.z + v0.w*d0.w
             + v1.x*d1.x + v1.y*d1.y + v1.z*d1.z + v1.w*d1.w;
    #pragma unroll
    for (int o = 4; o; o >>= 1) {
        ss += __shfl_xor_sync(0xffffffffu, ss, o);
        sd += __shfl_xor_sync(0xffffffffu, sd, o);
    }
    if ((lane & 7) == 0) {
        int head = lane >> 3;
        ssrc[w * 4 + head] = ss;
        sdst[w * 4 + head] = sd;
    }
}

// ------------------------- layer-2 scores: warp per node, 1 head ------------
__global__ void scores2_k(const float* __restrict__ h,
                          const float* __restrict__ asrc,
                          const float* __restrict__ adst,
                          float* __restrict__ ssrc, float* __restrict__ sdst)
{
    int w = (int)(((long)blockIdx.x * blockDim.x + threadIdx.x) >> 5);
    if (w >= NODES) return;
    int lane = threadIdx.x & 31;
    const float* row = h + (long)w * 64;
    float v1 = row[lane], v2 = row[lane + 32];
    float ss = v1 * asrc[lane] + v2 * asrc[lane + 32];
    float sd = v1 * adst[lane] + v2 * adst[lane + 32];
    #pragma unroll
    for (int o = 16; o; o >>= 1) {
        ss += __shfl_xor_sync(0xffffffffu, ss, o);
        sd += __shfl_xor_sync(0xffffffffu, sd, o);
    }
    if (lane == 0) { ssrc[w] = ss; sdst[w] = sd; }
}

// ------------------------- denom passes (no segment-max needed) -------------
__global__ void eden4_k() {
    long idx = (long)blockIdx.x * blockDim.x + threadIdx.x;
    if (idx >= (long)AUGE * 4) return;
    int i = (int)(idx >> 2), hh = (int)(idx & 3);
    int s, d;
    if (i < NEDGE) { s = g_ei[i]; d = g_ei[NEDGE + i]; } else { s = d = i - NEDGE; }
    float e = lrelu(g_ssrc1[s * 4 + hh] + g_sdst1[d * 4 + hh]);
    float ex = __expf(e);
    g_ex1[idx] = ex;
    atomicAdd(&g_den1[d * 4 + hh], ex);
}
__global__ void eden1_k() {
    int i = blockIdx.x * blockDim.x + threadIdx.x;
    if (i >= AUGE) return;
    int s, d;
    if (i < NEDGE) { s = g_ei[i]; d = g_ei[NEDGE + i]; } else { s = d = i - NEDGE; }
    float e = lrelu(g_ssrc2[s] + g_sdst2[d]);
    float ex = __expf(e);
    g_ex2[i] = ex;
    atomicAdd(&g_den2[d], ex);
}

// ------------------------- weighted aggregation (vectorized reds) -----------
__global__ void eagg1_k() {
    long tid = (long)blockIdx.x * blockDim.x + threadIdx.x;
    int w = (int)(tid >> 5);
    if (w >= AUGE) return;
    int lane = threadIdx.x & 31;
    int s, d;
    if (w < NEDGE) { s = g_ei[w]; d = g_ei[NEDGE + w]; } else { s = d = w - NEDGE; }
    float4 ex = *(const float4*)(g_ex1 + (long)w * 4);
    float4 dn = *(const float4*)(g_den1 + d * 4);
    float alpha[4];
    alpha[0] = ex.x / (dn.x + 1e-16f);
    alpha[1] = ex.y / (dn.y + 1e-16f);
    alpha[2] = ex.z / (dn.z + 1e-16f);
    alpha[3] = ex.w / (dn.w + 1e-16f);
    const float4* hp = (const float4*)(g_h1lin + (long)s * H1DIM);
    float4*       ap = (float4*)(g_agg1  + (long)d * H1DIM);
    #pragma unroll
    for (int q = lane; q < 64; q += 32) {
        float4 v = hp[q];
        float a = alpha[q >> 4];
        redAdd4(ap + q, make_float4(v.x * a, v.y * a, v.z * a, v.w * a));
    }
}
__global__ void eagg2_k() {
    long tid = (long)blockIdx.x * blockDim.x + threadIdx.x;
    int w = (int)(tid >> 4);
    if (w >= AUGE) return;
    int q = (int)(tid & 15);
    int s, d;
    if (w < NEDGE) { s = g_ei[w]; d = g_ei[NEDGE + w]; } else { s = d = w - NEDGE; }
    float alpha = g_ex2[w] / (g_den2[d] + 1e-16f);
    float4 v = ((const float4*)(g_h2lin + (long)s * HIDC))[q];
    redAdd4((float4*)(g_agg2 + (long)d * HIDC) + q,
            make_float4(v.x * alpha, v.y * alpha, v.z * alpha, v.w * alpha));
}

// ------------------------- per-edge MLP finish: warp per edge ---------------
__global__ void __launch_bounds__(256) edge_k(
    const float* __restrict__ PQ,
    const float* __restrict__ bm1, const float* __restrict__ Wm2,
    const float* __restrict__ bm2, float* __restrict__ out)
{
    long tid = (long)blockIdx.x * blockDim.x + threadIdx.x;
    int w = (int)(tid >> 5);
    if (w >= NEDGE) return;
    int lane = threadIdx.x & 31;
    int s = g_ei[w], d = g_ei[NEDGE + w];
    float2 p = *(const float2*)(PQ + (long)s * 128 + lane * 2);
    float2 q = *(const float2*)(PQ + (long)d * 128 + 64 + lane * 2);
    float2 b = *(const float2*)(bm1 + lane * 2);
    float h0 = fmaxf(p.x + q.x + b.x, 0.f);
    float h1 = fmaxf(p.y + q.y + b.y, 0.f);
    float4 w4 = *(const float4*)(Wm2 + lane * 4);
    float o0 = h0 * w4.x + h1 * w4.z;
    float o1 = h0 * w4.y + h1 * w4.w;
    #pragma unroll
    for (int off = 16; off; off >>= 1) {
        o0 += __shfl_xor_sync(0xffffffffu, o0, off);
        o1 += __shfl_xor_sync(0xffffffffu, o1, off);
    }
    if (lane == 0) {
        float2 r = make_float2(o0 + bm2[0], o1 + bm2[1]);
        *(float2*)(out + (long)w * 2) = r;
    }
}

// ------------------------- launch -------------------------------------------
extern "C" void kernel_launch(void* const* d_in, const int* in_sizes, int n_in,
                              void* d_out, int out_size)
{
    const float* x   = (const float*)d_in[0];
    const void*  eir = d_in[1];
    const float* W1  = (const float*)d_in[2];
    const float* as1 = (const float*)d_in[3];
    const float* ad1 = (const float*)d_in[4];
    const float* b1  = (const float*)d_in[5];
    const float* W2  = (const float*)d_in[6];
    const float* as2 = (const float*)d_in[7];
    const float* ad2 = (const float*)d_in[8];
    const float* b2  = (const float*)d_in[9];
    const float* Wm1 = (const float*)d_in[10];
    const float* bm1 = (const float*)d_in[11];
    const float* Wm2 = (const float*)d_in[12];
    const float* bm2 = (const float*)d_in[13];
    float* out = (float*)d_out;

    void* p;
    cudaGetSymbolAddress(&p, g_h1lin); float* h1lin = (float*)p;
    cudaGetSymbolAddress(&p, g_agg1);  float* agg1  = (float*)p;
    cudaGetSymbolAddress(&p, g_h2lin); float* h2lin = (float*)p;
    cudaGetSymbolAddress(&p, g_agg2);  float* agg2  = (float*)p;
    cudaGetSymbolAddress(&p, g_PQ);    float* PQ    = (float*)p;
    cudaGetSymbolAddress(&p, g_Bc);    float* Bc    = (float*)p;
    cudaGetSymbolAddress(&p, g_ssrc1); float* ssrc1 = (float*)p;
    cudaGetSymbolAddress(&p, g_sdst1); float* sdst1 = (float*)p;
    cudaGetSymbolAddress(&p, g_ssrc2); float* ssrc2 = (float*)p;
    cudaGetSymbolAddress(&p, g_sdst2); float* sdst2 = (float*)p;

    detect_k<<<1, 256>>>(eir);
    conv_k<<<(2 * NEDGE + 255) / 256, 256>>>(eir);
    setup_k<<<(int)(((long)NODES * H1DIM + 255) / 256), 256>>>(Wm1);

    // ---- layer 1 (4 heads, concat) ----
    gemm32_k<0><<<dim3((NODES + 63) / 64, H1DIM / 64), 256>>>(x, W1, nullptr, h1lin,
                                                              NODES, INC, H1DIM);
    scores1_k<<<(NODES * 32 + 255) / 256, 256>>>(h1lin, as1, ad1, ssrc1, sdst1);
    eden4_k<<<(int)(((long)AUGE * 4 + 255) / 256), 256>>>();
    eagg1_k<<<(int)(((long)AUGE * 32 + 255) / 256), 256>>>();

    // ---- layer 2 (1 head); relu(agg1+b1) fused into A-load ----
    gemm32_k<1><<<dim3((NODES + 63) / 64, 1), 256>>>(agg1, W2, b1, h2lin,
                                                     NODES, H1DIM, HIDC);
    scores2_k<<<(NODES * 32 + 255) / 256, 256>>>(h2lin, as2, ad2, ssrc2, sdst2);
    eden1_k<<<(AUGE + 255) / 256, 256>>>();
    eagg2_k<<<(int)(((long)AUGE * 16 + 255) / 256), 256>>>();

    // ---- edge MLP, factorized: PQ = (agg2+b2) @ [Wm1_top | Wm1_bot] ----
    gemm32_k<2><<<dim3((NODES + 63) / 64, 2), 256>>>(agg2, Bc, b2, PQ,
                                                     NODES, HIDC, 2 * HIDC);
    edge_k<<<(int)(((long)NEDGE * 32 + 255) / 256), 256>>>(PQ, bm1, Wm2, bm2, out);
}

// round 4
// speedup vs baseline: 1.2064x; 1.2064x over previous
#include <cuda_runtime.h>

#define NODES  50000
#define NEDGE  800000
#define AUGE   (NEDGE + NODES)     // 850000
#define INC    128
#define HIDC   64
#define NHEADS 4
#define H1DIM  (NHEADS * HIDC)     // 256

// ------------------------- scratch (static device memory) -------------------
__device__ float    g_h1lin[(size_t)NODES * H1DIM];
__device__ float    g_agg1 [(size_t)NODES * H1DIM];   // unnormalized
__device__ float    g_h2lin[(size_t)NODES * HIDC];
__device__ float    g_agg2 [(size_t)NODES * HIDC];    // unnormalized
__device__ float    g_PQ   [(size_t)NODES * 2 * HIDC];
__device__ float    g_Bc   [HIDC * 2 * HIDC];
__device__ float    g_ssrc1[NODES * NHEADS];
__device__ float    g_sdst1[NODES * NHEADS];
__device__ float    g_den1 [NODES * NHEADS];
__device__ float    g_ssrc2[NODES];
__device__ float    g_sdst2[NODES];
__device__ float    g_den2 [NODES];
__device__ int      g_ei   [2 * NEDGE];
__device__ int      g_is64;

// ------------------------- helpers ------------------------------------------
__device__ __forceinline__ void redAdd4(float4* p, float4 v) {
    asm volatile("red.global.add.v4.f32 [%0], {%1,%2,%3,%4};"
                 :: "l"(p), "f"(v.x), "f"(v.y), "f"(v.z), "f"(v.w) : "memory");
}
__device__ __forceinline__ float lrelu(float x) { return x >= 0.f ? x : 0.2f * x; }

// ------------------------- edge index dtype detect + normalize --------------
__global__ void detect_k(const void* p) {
    __shared__ int nz;
    if (threadIdx.x == 0) nz = 0;
    __syncthreads();
    const int2* q = (const int2*)p;
    for (int i = threadIdx.x; i < 4096; i += blockDim.x)
        if (q[i].y != 0) nz = 1;
    __syncthreads();
    if (threadIdx.x == 0) g_is64 = (nz == 0) ? 1 : 0;
}
__global__ void conv_k(const void* p) {
    int i = blockIdx.x * blockDim.x + threadIdx.x;
    if (i >= 2 * NEDGE) return;
    long long v = g_is64 ? ((const long long*)p)[i]
                         : (long long)((const int*)p)[i];
    g_ei[i] = (int)v;
}

// ------------------------- fused init + Wm1 repack --------------------------
__global__ void setup_k(const float* __restrict__ Wm1) {
    long i = (long)blockIdx.x * blockDim.x + threadIdx.x;
    if (i < (long)NODES * H1DIM) g_agg1[i] = 0.f;
    if (i < (long)NODES * HIDC)  g_agg2[i] = 0.f;
    if (i < NODES * NHEADS)      g_den1[i] = 0.f;
    if (i < NODES)               g_den2[i] = 0.f;
    if (i < HIDC * 2 * HIDC) {
        int k = (int)(i >> 7), j = (int)(i & 127);
        g_Bc[i] = (j < HIDC) ? Wm1[k * HIDC + j] : Wm1[(HIDC + k) * HIDC + (j - HIDC)];
    }
}

// ------------------------- scalar fp32 GEMM (64x64 tile, 4x4/thread) --------
// AMODE 0: plain A
// AMODE 1: relu(A/den1[r,head] + biasA[k])   (den per row*4+ (k>>6))
// AMODE 2: A/den2[r] + biasA[k]
template<int AMODE>
__global__ void __launch_bounds__(256) gemm64_k(
    const float* __restrict__ A, const float* __restrict__ B,
    const float* __restrict__ biasA, const float* __restrict__ den,
    float* __restrict__ C, int M, int K, int Nc)
{
    __shared__ float As[64][68];
    __shared__ float Bs[64][68];
    int t = threadIdx.x;
    int m0 = blockIdx.x * 64, n0 = blockIdx.y * 64;
    int tr = t >> 4, tc = t & 15;
    float acc[4][4] = {};
    for (int kt = 0; kt < K; kt += 64) {
        #pragma unroll
        for (int i = t; i < 1024; i += 256) {
            int r = i >> 4, c4 = (i & 15) << 2;
            int gr = m0 + r;
            float4 v = make_float4(0.f, 0.f, 0.f, 0.f);
            if (gr < M) {
                v = *(const float4*)(A + (long)gr * K + kt + c4);
                if (AMODE == 1) {
                    float dn = den[gr * 4 + ((kt + c4) >> 6)];
                    float inv = 1.f / (dn + 1e-16f);
                    float4 b = *(const float4*)(biasA + kt + c4);
                    v.x = fmaxf(v.x * inv + b.x, 0.f);
                    v.y = fmaxf(v.y * inv + b.y, 0.f);
                    v.z = fmaxf(v.z * inv + b.z, 0.f);
                    v.w = fmaxf(v.w * inv + b.w, 0.f);
                } else if (AMODE == 2) {
                    float inv = 1.f / (den[gr] + 1e-16f);
                    float4 b = *(const float4*)(biasA + kt + c4);
                    v.x = v.x * inv + b.x; v.y = v.y * inv + b.y;
                    v.z = v.z * inv + b.z; v.w = v.w * inv + b.w;
                }
            }
            *(float4*)&As[r][c4] = v;
        }
        #pragma unroll
        for (int i = t; i < 1024; i += 256) {
            int r = i >> 4, c4 = (i & 15) << 2;
            *(float4*)&Bs[r][c4] = *(const float4*)(B + (long)(kt + r) * Nc + n0 + c4);
        }
        __syncthreads();
        #pragma unroll
        for (int k4 = 0; k4 < 16; k4++) {
            float4 a4[4], b4[4];
            #pragma unroll
            for (int j = 0; j < 4; j++) a4[j] = *(const float4*)&As[tr * 4 + j][k4 * 4];
            #pragma unroll
            for (int kk = 0; kk < 4; kk++) b4[kk] = *(const float4*)&Bs[k4 * 4 + kk][tc * 4];
            #pragma unroll
            for (int j = 0; j < 4; j++) {
                float ax = a4[j].x, ay = a4[j].y, az = a4[j].z, aw = a4[j].w;
                acc[j][0] += ax * b4[0].x + ay * b4[1].x + az * b4[2].x + aw * b4[3].x;
                acc[j][1] += ax * b4[0].y + ay * b4[1].y + az * b4[2].y + aw * b4[3].y;
                acc[j][2] += ax * b4[0].z + ay * b4[1].z + az * b4[2].z + aw * b4[3].z;
                acc[j][3] += ax * b4[0].w + ay * b4[1].w + az * b4[2].w + aw * b4[3].w;
            }
        }
        __syncthreads();
    }
    #pragma unroll
    for (int j = 0; j < 4; j++) {
        int gr = m0 + tr * 4 + j;
        if (gr < M) {
            float4 v = make_float4(acc[j][0], acc[j][1], acc[j][2], acc[j][3]);
            *(float4*)(C + (long)gr * Nc + n0 + tc * 4) = v;
        }
    }
}

// ------------------------- layer-1 scores: warp per node, 4 heads -----------
__global__ void scores1_k(const float* __restrict__ h,
                          const float* __restrict__ asrc,
                          const float* __restrict__ adst,
                          float* __restrict__ ssrc, float* __restrict__ sdst)
{
    int w = (int)(((long)blockIdx.x * blockDim.x + threadIdx.x) >> 5);
    if (w >= NODES) return;
    int lane = threadIdx.x & 31;
    const float4* row = (const float4*)(h + (long)w * 256);
    float4 v0 = row[lane * 2], v1 = row[lane * 2 + 1];
    const float4* pa = (const float4*)asrc;
    const float4* pd = (const float4*)adst;
    float4 a0 = pa[lane * 2], a1 = pa[lane * 2 + 1];
    float4 d0 = pd[lane * 2], d1 = pd[lane * 2 + 1];
    float ss = v0.x*a0.x + v0.y*a0.y + v0.z*a0.z + v0.w*a0.w
             + v1.x*a1.x + v1.y*a1.y + v1.z*a1.z + v1.w*a1.w;
    float sd = v0.x*d0.x + v0.y*d0.y + v0.z*d0.z + v0.w*d0.w
             + v1.x*d1.x + v1.y*d1.y + v1.z*d1.z + v1.w*d1.w;
    #pragma unroll
    for (int o = 4; o; o >>= 1) {
        ss += __shfl_xor_sync(0xffffffffu, ss, o);
        sd += __shfl_xor_sync(0xffffffffu, sd, o);
    }
    if ((lane & 7) == 0) {
        int head = lane >> 3;
        ssrc[w * 4 + head] = ss;
        sdst[w * 4 + head] = sd;
    }
}

// ------------------------- layer-2 scores: warp per node, 1 head ------------
__global__ void scores2_k(const float* __restrict__ h,
                          const float* __restrict__ asrc,
                          const float* __restrict__ adst,
                          float* __restrict__ ssrc, float* __restrict__ sdst)
{
    int w = (int)(((long)blockIdx.x * blockDim.x + threadIdx.x) >> 5);
    if (w >= NODES) return;
    int lane = threadIdx.x & 31;
    const float* row = h + (long)w * 64;
    float v1 = row[lane], v2 = row[lane + 32];
    float ss = v1 * asrc[lane] + v2 * asrc[lane + 32];
    float sd = v1 * adst[lane] + v2 * adst[lane + 32];
    #pragma unroll
    for (int o = 16; o; o >>= 1) {
        ss += __shfl_xor_sync(0xffffffffu, ss, o);
        sd += __shfl_xor_sync(0xffffffffu, sd, o);
    }
    if (lane == 0) { ssrc[w] = ss; sdst[w] = sd; }
}

// -------- layer-1 fused softmax+aggregate: warp per edge, unnormalized ------
__global__ void eagg1f_k() {
    long tid = (long)blockIdx.x * blockDim.x + threadIdx.x;
    int w = (int)(tid >> 5);
    if (w >= AUGE) return;
    int lane = threadIdx.x & 31;
    int s, d;
    if (w < NEDGE) { s = g_ei[w]; d = g_ei[NEDGE + w]; } else { s = d = w - NEDGE; }
    float ex = 0.f;
    if (lane < 4) {
        float e = lrelu(g_ssrc1[s * 4 + lane] + g_sdst1[d * 4 + lane]);
        ex = __expf(e);
        atomicAdd(&g_den1[d * 4 + lane], ex);
    }
    const float4* hp = (const float4*)(g_h1lin + (long)s * H1DIM);
    float4*       ap = (float4*)(g_agg1  + (long)d * H1DIM);
    #pragma unroll
    for (int q = lane; q < 64; q += 32) {
        float a = __shfl_sync(0xffffffffu, ex, q >> 4);
        float4 v = hp[q];
        redAdd4(ap + q, make_float4(v.x * a, v.y * a, v.z * a, v.w * a));
    }
}

// -------- layer-2 fused softmax+aggregate: half-warp per edge ---------------
__global__ void eagg2f_k() {
    long tid = (long)blockIdx.x * blockDim.x + threadIdx.x;
    int w = (int)(tid >> 4);
    if (w >= AUGE) return;
    int lane = threadIdx.x & 31;
    int q = lane & 15;
    int s, d;
    if (w < NEDGE) { s = g_ei[w]; d = g_ei[NEDGE + w]; } else { s = d = w - NEDGE; }
    float ex = 0.f;
    if (q == 0) {
        float e = lrelu(g_ssrc2[s] + g_sdst2[d]);
        ex = __expf(e);
        atomicAdd(&g_den2[d], ex);
    }
    ex = __shfl_sync(0xffffffffu, ex, lane & 16);   // broadcast within half-warp
    float4 v = ((const float4*)(g_h2lin + (long)s * HIDC))[q];
    redAdd4((float4*)(g_agg2 + (long)d * HIDC) + q,
            make_float4(v.x * ex, v.y * ex, v.z * ex, v.w * ex));
}

// ------------------------- per-edge MLP finish: warp per edge ---------------
__global__ void __launch_bounds__(256) edge_k(
    const float* __restrict__ PQ,
    const float* __restrict__ bm1, const float* __restrict__ Wm2,
    const float* __restrict__ bm2, float* __restrict__ out)
{
    long tid = (long)blockIdx.x * blockDim.x + threadIdx.x;
    int w = (int)(tid >> 5);
    if (w >= NEDGE) return;
    int lane = threadIdx.x & 31;
    int s = g_ei[w], d = g_ei[NEDGE + w];
    float2 p = *(const float2*)(PQ + (long)s * 128 + lane * 2);
    float2 q = *(const float2*)(PQ + (long)d * 128 + 64 + lane * 2);
    float2 b = *(const float2*)(bm1 + lane * 2);
    float h0 = fmaxf(p.x + q.x + b.x, 0.f);
    float h1 = fmaxf(p.y + q.y + b.y, 0.f);
    float4 w4 = *(const float4*)(Wm2 + lane * 4);
    float o0 = h0 * w4.x + h1 * w4.z;
    float o1 = h0 * w4.y + h1 * w4.w;
    #pragma unroll
    for (int off = 16; off; off >>= 1) {
        o0 += __shfl_xor_sync(0xffffffffu, o0, off);
        o1 += __shfl_xor_sync(0xffffffffu, o1, off);
    }
    if (lane == 0) {
        float2 r = make_float2(o0 + bm2[0], o1 + bm2[1]);
        *(float2*)(out + (long)w * 2) = r;
    }
}

// ------------------------- launch -------------------------------------------
extern "C" void kernel_launch(void* const* d_in, const int* in_sizes, int n_in,
                              void* d_out, int out_size)
{
    const float* x   = (const float*)d_in[0];
    const void*  eir = d_in[1];
    const float* W1  = (const float*)d_in[2];
    const float* as1 = (const float*)d_in[3];
    const float* ad1 = (const float*)d_in[4];
    const float* b1  = (const float*)d_in[5];
    const float* W2  = (const float*)d_in[6];
    const float* as2 = (const float*)d_in[7];
    const float* ad2 = (const float*)d_in[8];
    const float* b2  = (const float*)d_in[9];
    const float* Wm1 = (const float*)d_in[10];
    const float* bm1 = (const float*)d_in[11];
    const float* Wm2 = (const float*)d_in[12];
    const float* bm2 = (const float*)d_in[13];
    float* out = (float*)d_out;

    void* p;
    cudaGetSymbolAddress(&p, g_h1lin); float* h1lin = (float*)p;
    cudaGetSymbolAddress(&p, g_agg1);  float* agg1  = (float*)p;
    cudaGetSymbolAddress(&p, g_h2lin); float* h2lin = (float*)p;
    cudaGetSymbolAddress(&p, g_agg2);  float* agg2  = (float*)p;
    cudaGetSymbolAddress(&p, g_PQ);    float* PQ    = (float*)p;
    cudaGetSymbolAddress(&p, g_Bc);    float* Bc    = (float*)p;
    cudaGetSymbolAddress(&p, g_ssrc1); float* ssrc1 = (float*)p;
    cudaGetSymbolAddress(&p, g_sdst1); float* sdst1 = (float*)p;
    cudaGetSymbolAddress(&p, g_den1);  float* den1  = (float*)p;
    cudaGetSymbolAddress(&p, g_ssrc2); float* ssrc2 = (float*)p;
    cudaGetSymbolAddress(&p, g_sdst2); float* sdst2 = (float*)p;
    cudaGetSymbolAddress(&p, g_den2);  float* den2  = (float*)p;

    detect_k<<<1, 256>>>(eir);
    conv_k<<<(2 * NEDGE + 255) / 256, 256>>>(eir);
    setup_k<<<(int)(((long)NODES * H1DIM + 255) / 256), 256>>>(Wm1);

    // ---- layer 1 (4 heads, concat) ----
    gemm64_k<0><<<dim3((NODES + 63) / 64, H1DIM / 64), 256>>>(
        x, W1, nullptr, nullptr, h1lin, NODES, INC, H1DIM);
    scores1_k<<<(NODES * 32 + 255) / 256, 256>>>(h1lin, as1, ad1, ssrc1, sdst1);
    eagg1f_k<<<(int)(((long)AUGE * 32 + 255) / 256), 256>>>();

    // ---- layer 2; relu(agg1/den1 + b1) fused into A-load ----
    gemm64_k<1><<<dim3((NODES + 63) / 64, 1), 256>>>(
        agg1, W2, b1, den1, h2lin, NODES, H1DIM, HIDC);
    scores2_k<<<(NODES * 32 + 255) / 256, 256>>>(h2lin, as2, ad2, ssrc2, sdst2);
    eagg2f_k<<<(int)(((long)AUGE * 16 + 255) / 256), 256>>>();

    // ---- edge MLP, factorized: PQ = (agg2/den2 + b2) @ [Wm1_top | Wm1_bot] ----
    gemm64_k<2><<<dim3((NODES + 63) / 64, 2), 256>>>(
        agg2, Bc, b2, den2, PQ, NODES, HIDC, 2 * HIDC);
    edge_k<<<(int)(((long)NEDGE * 32 + 255) / 256), 256>>>(PQ, bm1, Wm2, bm2, out);
}

// round 5
// speedup vs baseline: 1.2811x; 1.0620x over previous
#include <cuda_runtime.h>

#define NODES  50000
#define NEDGE  800000
#define AUGE   (NEDGE + NODES)     // 850000
#define INC    128
#define HIDC   64
#define NHEADS 4
#define H1DIM  (NHEADS * HIDC)     // 256

// ------------------------- scratch (static device memory) -------------------
__device__ float    g_h1lin[(size_t)NODES * H1DIM];
__device__ float    g_agg1 [(size_t)NODES * H1DIM];   // unnormalized
__device__ float    g_h2lin[(size_t)NODES * HIDC];
__device__ float    g_agg2 [(size_t)NODES * HIDC];    // unnormalized
__device__ float    g_PQ   [(size_t)NODES * 2 * HIDC];
__device__ float    g_Bc   [HIDC * 2 * HIDC];
__device__ float    g_ssrc1[NODES * NHEADS];
__device__ float    g_sdst1[NODES * NHEADS];
__device__ float    g_den1 [NODES * NHEADS];
__device__ float    g_ssrc2[NODES];
__device__ float    g_sdst2[NODES];
__device__ float    g_den2 [NODES];
__device__ int      g_ei   [2 * NEDGE];
__device__ int      g_deg  [NODES];
__device__ int      g_rowp [NODES];
__device__ int      g_pos  [NODES];
__device__ int      g_srt  [AUGE];     // src ids sorted by dst
__device__ int      g_is64;

// ------------------------- helpers ------------------------------------------
__device__ __forceinline__ float lrelu(float x) { return x >= 0.f ? x : 0.2f * x; }

// ------------------------- edge index dtype detect + normalize --------------
__global__ void detect_k(const void* p) {
    __shared__ int nz;
    if (threadIdx.x == 0) nz = 0;
    __syncthreads();
    const int2* q = (const int2*)p;
    for (int i = threadIdx.x; i < 4096; i += blockDim.x)
        if (q[i].y != 0) nz = 1;
    __syncthreads();
    if (threadIdx.x == 0) g_is64 = (nz == 0) ? 1 : 0;
}
__global__ void conv_k(const void* p) {
    int i = blockIdx.x * blockDim.x + threadIdx.x;
    if (i >= 2 * NEDGE) return;
    long long v = g_is64 ? ((const long long*)p)[i]
                         : (long long)((const int*)p)[i];
    g_ei[i] = (int)v;
}

// ------------------------- setup: zero degrees + repack Wm1 -----------------
__global__ void setup_k(const float* __restrict__ Wm1) {
    int i = blockIdx.x * blockDim.x + threadIdx.x;
    if (i < NODES) g_deg[i] = 0;
    if (i < HIDC * 2 * HIDC) {
        int k = i >> 7, j = i & 127;
        g_Bc[i] = (j < HIDC) ? Wm1[k * HIDC + j] : Wm1[(HIDC + k) * HIDC + (j - HIDC)];
    }
}

// ------------------------- CSR build ----------------------------------------
__global__ void hist_k() {
    int i = blockIdx.x * blockDim.x + threadIdx.x;
    if (i >= AUGE) return;
    int d = (i < NEDGE) ? g_ei[NEDGE + i] : i - NEDGE;
    atomicAdd(&g_deg[d], 1);
}
__global__ void __launch_bounds__(1024) scan_k() {
    __shared__ int part[1024];
    int t = threadIdx.x;
    const int CH = (NODES + 1023) / 1024;
    int base = t * CH;
    int sum = 0;
    for (int i = 0; i < CH; i++) {
        int idx = base + i;
        if (idx < NODES) sum += g_deg[idx];
    }
    part[t] = sum;
    __syncthreads();
    int total = sum;
    for (int off = 1; off < 1024; off <<= 1) {
        int v = (t >= off) ? part[t - off] : 0;
        __syncthreads();
        part[t] += v;
        __syncthreads();
    }
    int run = part[t] - total;   // exclusive prefix for this chunk
    for (int i = 0; i < CH; i++) {
        int idx = base + i;
        if (idx < NODES) {
            g_rowp[idx] = run;
            g_pos[idx]  = run;
            run += g_deg[idx];
        }
    }
}
__global__ void scatter_k() {
    int i = blockIdx.x * blockDim.x + threadIdx.x;
    if (i >= AUGE) return;
    int s, d;
    if (i < NEDGE) { s = g_ei[i]; d = g_ei[NEDGE + i]; } else { s = d = i - NEDGE; }
    int p = atomicAdd(&g_pos[d], 1);
    g_srt[p] = s;
}

// ------------------------- scalar fp32 GEMM (64x64 tile, 4x4/thread) --------
// AMODE 0: plain A
// AMODE 1: relu(A/den1[r,head] + biasA[k])
// AMODE 2: A/den2[r] + biasA[k]
template<int AMODE>
__global__ void __launch_bounds__(256) gemm64_k(
    const float* __restrict__ A, const float* __restrict__ B,
    const float* __restrict__ biasA, const float* __restrict__ den,
    float* __restrict__ C, int M, int K, int Nc)
{
    __shared__ float As[64][68];
    __shared__ float Bs[64][68];
    int t = threadIdx.x;
    int m0 = blockIdx.x * 64, n0 = blockIdx.y * 64;
    int tr = t >> 4, tc = t & 15;
    float acc[4][4] = {};
    for (int kt = 0; kt < K; kt += 64) {
        #pragma unroll
        for (int i = t; i < 1024; i += 256) {
            int r = i >> 4, c4 = (i & 15) << 2;
            int gr = m0 + r;
            float4 v = make_float4(0.f, 0.f, 0.f, 0.f);
            if (gr < M) {
                v = *(const float4*)(A + (long)gr * K + kt + c4);
                if (AMODE == 1) {
                    float dn = den[gr * 4 + ((kt + c4) >> 6)];
                    float inv = 1.f / (dn + 1e-16f);
                    float4 b = *(const float4*)(biasA + kt + c4);
                    v.x = fmaxf(v.x * inv + b.x, 0.f);
                    v.y = fmaxf(v.y * inv + b.y, 0.f);
                    v.z = fmaxf(v.z * inv + b.z, 0.f);
                    v.w = fmaxf(v.w * inv + b.w, 0.f);
                } else if (AMODE == 2) {
                    float inv = 1.f / (den[gr] + 1e-16f);
                    float4 b = *(const float4*)(biasA + kt + c4);
                    v.x = v.x * inv + b.x; v.y = v.y * inv + b.y;
                    v.z = v.z * inv + b.z; v.w = v.w * inv + b.w;
                }
            }
            *(float4*)&As[r][c4] = v;
        }
        #pragma unroll
        for (int i = t; i < 1024; i += 256) {
            int r = i >> 4, c4 = (i & 15) << 2;
            *(float4*)&Bs[r][c4] = *(const float4*)(B + (long)(kt + r) * Nc + n0 + c4);
        }
        __syncthreads();
        #pragma unroll
        for (int k4 = 0; k4 < 16; k4++) {
            float4 a4[4], b4[4];
            #pragma unroll
            for (int j = 0; j < 4; j++) a4[j] = *(const float4*)&As[tr * 4 + j][k4 * 4];
            #pragma unroll
            for (int kk = 0; kk < 4; kk++) b4[kk] = *(const float4*)&Bs[k4 * 4 + kk][tc * 4];
            #pragma unroll
            for (int j = 0; j < 4; j++) {
                float ax = a4[j].x, ay = a4[j].y, az = a4[j].z, aw = a4[j].w;
                acc[j][0] += ax * b4[0].x + ay * b4[1].x + az * b4[2].x + aw * b4[3].x;
                acc[j][1] += ax * b4[0].y + ay * b4[1].y + az * b4[2].y + aw * b4[3].y;
                acc[j][2] += ax * b4[0].z + ay * b4[1].z + az * b4[2].z + aw * b4[3].z;
                acc[j][3] += ax * b4[0].w + ay * b4[1].w + az * b4[2].w + aw * b4[3].w;
            }
        }
        __syncthreads();
    }
    #pragma unroll
    for (int j = 0; j < 4; j++) {
        int gr = m0 + tr * 4 + j;
        if (gr < M) {
            float4 v = make_float4(acc[j][0], acc[j][1], acc[j][2], acc[j][3]);
            *(float4*)(C + (long)gr * Nc + n0 + tc * 4) = v;
        }
    }
}

// ------------------------- layer-1 scores: warp per node, 4 heads -----------
__global__ void scores1_k(const float* __restrict__ h,
                          const float* __restrict__ asrc,
                          const float* __restrict__ adst,
                          float* __restrict__ ssrc, float* __restrict__ sdst)
{
    int w = (int)(((long)blockIdx.x * blockDim.x + threadIdx.x) >> 5);
    if (w >= NODES) return;
    int lane = threadIdx.x & 31;
    const float4* row = (const float4*)(h + (long)w * 256);
    float4 v0 = row[lane * 2], v1 = row[lane * 2 + 1];
    const float4* pa = (const float4*)asrc;
    const float4* pd = (const float4*)adst;
    float4 a0 = pa[lane * 2], a1 = pa[lane * 2 + 1];
    float4 d0 = pd[lane * 2], d1 = pd[lane * 2 + 1];
    float ss = v0.x*a0.x + v0.y*a0.y + v0.z*a0.z + v0.w*a0.w
             + v1.x*a1.x + v1.y*a1.y + v1.z*a1.z + v1.w*a1.w;
    float sd = v0.x*d0.x + v0.y*d0.y + v0.z*d0.z + v0.w*d0.w
             + v1.x*d1.x + v1.y*d1.y + v1.z*d1.z + v1.w*d1.w;
    #pragma unroll
    for (int o = 4; o; o >>= 1) {
        ss += __shfl_xor_sync(0xffffffffu, ss, o);
        sd += __shfl_xor_sync(0xffffffffu, sd, o);
    }
    if ((lane & 7) == 0) {
        int head = lane >> 3;
        ssrc[w * 4 + head] = ss;
        sdst[w * 4 + head] = sd;
    }
}

// ------------------------- layer-2 scores: warp per node, 1 head ------------
__global__ void scores2_k(const float* __restrict__ h,
                          const float* __restrict__ asrc,
                          const float* __restrict__ adst,
                          float* __restrict__ ssrc, float* __restrict__ sdst)
{
    int w = (int)(((long)blockIdx.x * blockDim.x + threadIdx.x) >> 5);
    if (w >= NODES) return;
    int lane = threadIdx.x & 31;
    const float* row = h + (long)w * 64;
    float v1 = row[lane], v2 = row[lane + 32];
    float ss = v1 * asrc[lane] + v2 * asrc[lane + 32];
    float sd = v1 * adst[lane] + v2 * adst[lane + 32];
    #pragma unroll
    for (int o = 16; o; o >>= 1) {
        ss += __shfl_xor_sync(0xffffffffu, ss, o);
        sd += __shfl_xor_sync(0xffffffffu, sd, o);
    }
    if (lane == 0) { ssrc[w] = ss; sdst[w] = sd; }
}

// -------- layer-1 CSR aggregation: warp per dst node, register acc ----------
__global__ void __launch_bounds__(256) eagg1c_k() {
    int node = (int)(((long)blockIdx.x * blockDim.x + threadIdx.x) >> 5);
    if (node >= NODES) return;
    int lane = threadIdx.x & 31;
    int start = g_rowp[node], deg = g_deg[node];
    float sdv = (lane < 4) ? g_sdst1[node * 4 + lane] : 0.f;
    int ha = lane >> 4, hb = ha + 2;      // heads for cols q=lane, q=lane+32
    float4 accA = make_float4(0.f, 0.f, 0.f, 0.f);
    float4 accB = make_float4(0.f, 0.f, 0.f, 0.f);
    float den = 0.f;
    for (int e = 0; e < deg; e++) {
        int s = g_srt[start + e];
        float ex = 0.f;
        if (lane < 4) {
            float sc = g_ssrc1[s * 4 + lane] + sdv;
            ex = __expf(lrelu(sc));
            den += ex;
        }
        float exa = __shfl_sync(0xffffffffu, ex, ha);
        float exb = __shfl_sync(0xffffffffu, ex, hb);
        const float4* hp = (const float4*)(g_h1lin + (long)s * H1DIM);
        float4 v0 = hp[lane], v1 = hp[lane + 32];
        accA.x += v0.x * exa; accA.y += v0.y * exa;
        accA.z += v0.z * exa; accA.w += v0.w * exa;
        accB.x += v1.x * exb; accB.y += v1.y * exb;
        accB.z += v1.z * exb; accB.w += v1.w * exb;
    }
    float4* ap = (float4*)(g_agg1 + (long)node * H1DIM);
    ap[lane] = accA;
    ap[lane + 32] = accB;
    if (lane < 4) g_den1[node * 4 + lane] = den;
}

// -------- layer-2 CSR aggregation: warp per dst node -------------------------
__global__ void __launch_bounds__(256) eagg2c_k() {
    int node = (int)(((long)blockIdx.x * blockDim.x + threadIdx.x) >> 5);
    if (node >= NODES) return;
    int lane = threadIdx.x & 31;
    int start = g_rowp[node], deg = g_deg[node];
    float sdv = (lane == 0) ? g_sdst2[node] : 0.f;
    float a0 = 0.f, a1 = 0.f, den = 0.f;
    for (int e = 0; e < deg; e++) {
        int s = g_srt[start + e];
        float ex = 0.f;
        if (lane == 0) {
            ex = __expf(lrelu(g_ssrc2[s] + sdv));
            den += ex;
        }
        ex = __shfl_sync(0xffffffffu, ex, 0);
        float2 v = ((const float2*)(g_h2lin + (long)s * HIDC))[lane];
        a0 += v.x * ex; a1 += v.y * ex;
    }
    ((float2*)(g_agg2 + (long)node * HIDC))[lane] = make_float2(a0, a1);
    if (lane == 0) g_den2[node] = den;
}

// ------------------------- per-edge MLP finish: warp per edge ---------------
__global__ void __launch_bounds__(256) edge_k(
    const float* __restrict__ PQ,
    const float* __restrict__ bm1, const float* __restrict__ Wm2,
    const float* __restrict__ bm2, float* __restrict__ out)
{
    long tid = (long)blockIdx.x * blockDim.x + threadIdx.x;
    int w = (int)(tid >> 5);
    if (w >= NEDGE) return;
    int lane = threadIdx.x & 31;
    int s = g_ei[w], d = g_ei[NEDGE + w];
    float2 p = *(const float2*)(PQ + (long)s * 128 + lane * 2);
    float2 q = *(const float2*)(PQ + (long)d * 128 + 64 + lane * 2);
    float2 b = *(const float2*)(bm1 + lane * 2);
    float h0 = fmaxf(p.x + q.x + b.x, 0.f);
    float h1 = fmaxf(p.y + q.y + b.y, 0.f);
    float4 w4 = *(const float4*)(Wm2 + lane * 4);
    float o0 = h0 * w4.x + h1 * w4.z;
    float o1 = h0 * w4.y + h1 * w4.w;
    #pragma unroll
    for (int off = 16; off; off >>= 1) {
        o0 += __shfl_xor_sync(0xffffffffu, o0, off);
        o1 += __shfl_xor_sync(0xffffffffu, o1, off);
    }
    if (lane == 0) {
        float2 r = make_float2(o0 + bm2[0], o1 + bm2[1]);
        *(float2*)(out + (long)w * 2) = r;
    }
}

// ------------------------- launch -------------------------------------------
extern "C" void kernel_launch(void* const* d_in, const int* in_sizes, int n_in,
                              void* d_out, int out_size)
{
    const float* x   = (const float*)d_in[0];
    const void*  eir = d_in[1];
    const float* W1  = (const float*)d_in[2];
    const float* as1 = (const float*)d_in[3];
    const float* ad1 = (const float*)d_in[4];
    const float* b1  = (const float*)d_in[5];
    const float* W2  = (const float*)d_in[6];
    const float* as2 = (const float*)d_in[7];
    const float* ad2 = (const float*)d_in[8];
    const float* b2  = (const float*)d_in[9];
    const float* Wm1 = (const float*)d_in[10];
    const float* bm1 = (const float*)d_in[11];
    const float* Wm2 = (const float*)d_in[12];
    const float* bm2 = (const float*)d_in[13];
    float* out = (float*)d_out;

    void* p;
    cudaGetSymbolAddress(&p, g_h1lin); float* h1lin = (float*)p;
    cudaGetSymbolAddress(&p, g_agg1);  float* agg1  = (float*)p;
    cudaGetSymbolAddress(&p, g_h2lin); float* h2lin = (float*)p;
    cudaGetSymbolAddress(&p, g_agg2);  float* agg2  = (float*)p;
    cudaGetSymbolAddress(&p, g_PQ);    float* PQ    = (float*)p;
    cudaGetSymbolAddress(&p, g_Bc);    float* Bc    = (float*)p;
    cudaGetSymbolAddress(&p, g_ssrc1); float* ssrc1 = (float*)p;
    cudaGetSymbolAddress(&p, g_sdst1); float* sdst1 = (float*)p;
    cudaGetSymbolAddress(&p, g_den1);  float* den1  = (float*)p;
    cudaGetSymbolAddress(&p, g_ssrc2); float* ssrc2 = (float*)p;
    cudaGetSymbolAddress(&p, g_sdst2); float* sdst2 = (float*)p;
    cudaGetSymbolAddress(&p, g_den2);  float* den2  = (float*)p;

    detect_k<<<1, 256>>>(eir);
    conv_k<<<(2 * NEDGE + 255) / 256, 256>>>(eir);
    setup_k<<<(NODES + 255) / 256, 256>>>(Wm1);
    hist_k<<<(AUGE + 255) / 256, 256>>>();
    scan_k<<<1, 1024>>>();
    scatter_k<<<(AUGE + 255) / 256, 256>>>();

    // ---- layer 1 (4 heads, concat) ----
    gemm64_k<0><<<dim3((NODES + 63) / 64, H1DIM / 64), 256>>>(
        x, W1, nullptr, nullptr, h1lin, NODES, INC, H1DIM);
    scores1_k<<<(NODES * 32 + 255) / 256, 256>>>(h1lin, as1, ad1, ssrc1, sdst1);
    eagg1c_k<<<(NODES * 32 + 255) / 256, 256>>>();

    // ---- layer 2; relu(agg1/den1 + b1) fused into A-load ----
    gemm64_k<1><<<dim3((NODES + 63) / 64, 1), 256>>>(
        agg1, W2, b1, den1, h2lin, NODES, H1DIM, HIDC);
    scores2_k<<<(NODES * 32 + 255) / 256, 256>>>(h2lin, as2, ad2, ssrc2, sdst2);
    eagg2c_k<<<(NODES * 32 + 255) / 256, 256>>>();

    // ---- edge MLP, factorized: PQ = (agg2/den2 + b2) @ [Wm1_top | Wm1_bot] ----
    gemm64_k<2><<<dim3((NODES + 63) / 64, 2), 256>>>(
        agg2, Bc, b2, den2, PQ, NODES, HIDC, 2 * HIDC);
    edge_k<<<(int)(((long)NEDGE * 32 + 255) / 256), 256>>>(PQ, bm1, Wm2, bm2, out);
}

// round 6
// speedup vs baseline: 1.4787x; 1.1543x over previous
#include <cuda_runtime.h>

#define NODES  50000
#define NEDGE  800000
#define AUGE   (NEDGE + NODES)     // 850000
#define INC    128
#define HIDC   64
#define NHEADS 4
#define H1DIM  (NHEADS * HIDC)     // 256

// ------------------------- scratch (static device memory) -------------------
__device__ float    g_h1lin[(size_t)NODES * H1DIM];
__device__ float    g_agg1 [(size_t)NODES * H1DIM];   // unnormalized
__device__ float    g_h2lin[(size_t)NODES * HIDC];
__device__ float    g_agg2 [(size_t)NODES * HIDC];    // unnormalized
__device__ float    g_PQ   [(size_t)NODES * 2 * HIDC];
__device__ float    g_Bc   [HIDC * 2 * HIDC];
__device__ float    g_ssrc1[NODES * NHEADS];
__device__ float    g_sdst1[NODES * NHEADS];
__device__ float    g_den1 [NODES * NHEADS];
__device__ float    g_ssrc2[NODES];
__device__ float    g_sdst2[NODES];
__device__ float    g_den2 [NODES];
__device__ int      g_ei   [2 * NEDGE];
__device__ int      g_deg  [NODES];
__device__ int      g_rowp [NODES];
__device__ int      g_pos  [NODES];
__device__ int      g_srt  [AUGE];     // src ids sorted by dst
__device__ int      g_is64;

// ------------------------- helpers ------------------------------------------
__device__ __forceinline__ float lrelu(float x) { return x >= 0.f ? x : 0.2f * x; }
__device__ __forceinline__ unsigned t32(float x) {
    unsigned r; asm("cvt.rna.tf32.f32 %0, %1;" : "=r"(r) : "f"(x)); return r;
}
__device__ __forceinline__ void mma_tf32(float4& d, const unsigned* a,
                                         unsigned b0, unsigned b1) {
    asm("mma.sync.aligned.m16n8k8.row.col.f32.tf32.tf32.f32 "
        "{%0,%1,%2,%3},{%4,%5,%6,%7},{%8,%9},{%0,%1,%2,%3};"
        : "+f"(d.x), "+f"(d.y), "+f"(d.z), "+f"(d.w)
        : "r"(a[0]), "r"(a[1]), "r"(a[2]), "r"(a[3]), "r"(b0), "r"(b1));
}

// ------------------------- edge index dtype detect + normalize --------------
__global__ void detect_k(const void* p) {
    __shared__ int nz;
    if (threadIdx.x == 0) nz = 0;
    __syncthreads();
    const int2* q = (const int2*)p;
    for (int i = threadIdx.x; i < 4096; i += blockDim.x)
        if (q[i].y != 0) nz = 1;
    __syncthreads();
    if (threadIdx.x == 0) g_is64 = (nz == 0) ? 1 : 0;
}
// conv + degree histogram fused (g_deg pre-seeded to 1 for self-loops)
__global__ void conv_k(const void* p) {
    int i = blockIdx.x * blockDim.x + threadIdx.x;
    if (i >= 2 * NEDGE) return;
    long long v = g_is64 ? ((const long long*)p)[i]
                         : (long long)((const int*)p)[i];
    int vi = (int)v;
    g_ei[i] = vi;
    if (i >= NEDGE) atomicAdd(&g_deg[vi], 1);
}

// ------------------------- setup: seed degrees + repack Wm1 -----------------
__global__ void setup_k(const float* __restrict__ Wm1) {
    int i = blockIdx.x * blockDim.x + threadIdx.x;
    if (i < NODES) g_deg[i] = 1;   // self-loop
    if (i < HIDC * 2 * HIDC) {
        int k = i >> 7, j = i & 127;
        g_Bc[i] = (j < HIDC) ? Wm1[k * HIDC + j] : Wm1[(HIDC + k) * HIDC + (j - HIDC)];
    }
}

// ------------------------- CSR build ----------------------------------------
__global__ void __launch_bounds__(1024) scan_k() {
    __shared__ int part[1024];
    int t = threadIdx.x;
    const int CH = (NODES + 1023) / 1024;
    int base = t * CH;
    int sum = 0;
    for (int i = 0; i < CH; i++) {
        int idx = base + i;
        if (idx < NODES) sum += g_deg[idx];
    }
    part[t] = sum;
    __syncthreads();
    int total = sum;
    for (int off = 1; off < 1024; off <<= 1) {
        int v = (t >= off) ? part[t - off] : 0;
        __syncthreads();
        part[t] += v;
        __syncthreads();
    }
    int run = part[t] - total;
    for (int i = 0; i < CH; i++) {
        int idx = base + i;
        if (idx < NODES) {
            g_rowp[idx] = run;
            g_pos[idx]  = run;
            run += g_deg[idx];
        }
    }
}
__global__ void scatter_k() {
    int i = blockIdx.x * blockDim.x + threadIdx.x;
    if (i >= AUGE) return;
    int s, d;
    if (i < NEDGE) { s = g_ei[i]; d = g_ei[NEDGE + i]; } else { s = d = i - NEDGE; }
    int p = atomicAdd(&g_pos[d], 1);
    g_srt[p] = s;
}

// ---------------- tf32 tensor-core GEMM: 128x64 block, BK=32 ----------------
// 8 warps = 4(m) x 2(n); warp tile 32m x 32n; mma m16n8k8.
// AMODE 0: plain A; 1: relu(A/den[r,(k>>6)] + biasA[k]); 2: A/den[r] + biasA[k]
template<int AMODE>
__global__ void __launch_bounds__(256) gemmt_k(
    const float* __restrict__ A, const float* __restrict__ B,
    const float* __restrict__ biasA, const float* __restrict__ den,
    float* __restrict__ C, int M, int K, int Nc)
{
    // A fragments: [kstep(4)][mtile(8)][lane(32, ^kstep)][j(4)]
    __shared__ unsigned Asm[4 * 8 * 32 * 4];      // 16KB
    // B fragments: [plane(2)][kstep(4)][g(2)][lane(32)][4]
    __shared__ unsigned Bsm[2 * 4 * 2 * 32 * 4];  // 8KB
    int t = threadIdx.x;
    int lane = t & 31, warp = t >> 5;
    int wm = warp >> 1, wn = warp & 1;
    int m0 = blockIdx.x * 128, n0 = blockIdx.y * 64;

    float4 acc[2][4];
    #pragma unroll
    for (int i = 0; i < 2; i++)
        #pragma unroll
        for (int j = 0; j < 4; j++) acc[i][j] = make_float4(0.f, 0.f, 0.f, 0.f);

    for (int k0 = 0; k0 < K; k0 += 32) {
        // ---- load A tile 128x32 into fragment layout ----
        #pragma unroll
        for (int i = t; i < 1024; i += 256) {
            int r = i >> 3;                 // 0..127
            int kq = (i & 7) << 2;          // 0,4,...,28
            int gr = m0 + r;
            float4 v = make_float4(0.f, 0.f, 0.f, 0.f);
            if (gr < M) {
                v = *(const float4*)(A + (long)gr * K + k0 + kq);
                if (AMODE == 1) {
                    float inv = 1.f / (den[gr * 4 + ((k0 + kq) >> 6)] + 1e-16f);
                    float4 b = *(const float4*)(biasA + k0 + kq);
                    v.x = fmaxf(v.x * inv + b.x, 0.f);
                    v.y = fmaxf(v.y * inv + b.y, 0.f);
                    v.z = fmaxf(v.z * inv + b.z, 0.f);
                    v.w = fmaxf(v.w * inv + b.w, 0.f);
                } else if (AMODE == 2) {
                    float inv = 1.f / (den[gr] + 1e-16f);
                    float4 b = *(const float4*)(biasA + k0 + kq);
                    v.x = v.x * inv + b.x; v.y = v.y * inv + b.y;
                    v.z = v.z * inv + b.z; v.w = v.w * inv + b.w;
                }
            }
            int kstep = kq >> 3;
            int mtile = r >> 4, rr = r & 15;
            int j = (rr >= 8 ? 1 : 0) + ((kq & 4) ? 2 : 0);
            int lane0 = (rr & 7) << 2;
            unsigned* bp = Asm + (((kstep * 8 + mtile) * 32) + lane0) * 4 + j;
            bp[(0 ^ kstep) * 4] = t32(v.x);
            bp[(1 ^ kstep) * 4] = t32(v.y);
            bp[(2 ^ kstep) * 4] = t32(v.z);
            bp[(3 ^ kstep) * 4] = t32(v.w);
        }
        // ---- load B tile 32x64 into fragment layout ----
        #pragma unroll
        for (int i = t; i < 512; i += 256) {
            int kk = i >> 4;                // 0..31
            int nq = (i & 15) << 2;         // 0..60
            float4 v = *(const float4*)(B + (long)(k0 + kk) * Nc + n0 + nq);
            int kstep = kk >> 3, klo = kk & 3, bsel = ((kk & 7) >= 4);
            unsigned tv[4] = { t32(v.x), t32(v.y), t32(v.z), t32(v.w) };
            #pragma unroll
            for (int c = 0; c < 4; c++) {
                int ng = nq + c;
                int g = ng >> 5, nn = ng & 31, tt = nn >> 3;
                int ln = ((nn & 7) << 2) | klo;
                Bsm[(tt >> 1) * 1024 + (((kstep * 2 + g) * 32) + ln) * 4
                    + (tt & 1) * 2 + bsel] = tv[c];
            }
        }
        __syncthreads();
        // ---- compute ----
        #pragma unroll
        for (int kstep = 0; kstep < 4; kstep++) {
            unsigned a[2][4], b[8];
            #pragma unroll
            for (int i = 0; i < 2; i++)
                *(uint4*)a[i] = *(const uint4*)
                    &Asm[(((kstep * 8) + (wm * 2 + i)) * 32 + (lane ^ kstep)) * 4];
            *(uint4*)&b[0] = *(const uint4*)&Bsm[(((kstep * 2 + wn) * 32) + lane) * 4];
            *(uint4*)&b[4] = *(const uint4*)&Bsm[1024 + (((kstep * 2 + wn) * 32) + lane) * 4];
            #pragma unroll
            for (int i = 0; i < 2; i++) {
                mma_tf32(acc[i][0], a[i], b[0], b[1]);
                mma_tf32(acc[i][1], a[i], b[2], b[3]);
                mma_tf32(acc[i][2], a[i], b[4], b[5]);
                mma_tf32(acc[i][3], a[i], b[6], b[7]);
            }
        }
        __syncthreads();
    }
    // ---- epilogue ----
    int mw = m0 + wm * 32;
    int nw = n0 + wn * 32;
    #pragma unroll
    for (int i = 0; i < 2; i++) {
        int rlo = mw + i * 16 + (lane >> 2);
        int rhi = rlo + 8;
        #pragma unroll
        for (int tt = 0; tt < 4; tt++) {
            int col = nw + tt * 8 + (lane & 3) * 2;
            if (rlo < M)
                *(float2*)(C + (long)rlo * Nc + col) = make_float2(acc[i][tt].x, acc[i][tt].y);
            if (rhi < M)
                *(float2*)(C + (long)rhi * Nc + col) = make_float2(acc[i][tt].z, acc[i][tt].w);
        }
    }
}

// ------------------------- layer-1 scores: warp per node, 4 heads -----------
__global__ void scores1_k(const float* __restrict__ h,
                          const float* __restrict__ asrc,
                          const float* __restrict__ adst,
                          float* __restrict__ ssrc, float* __restrict__ sdst)
{
    int w = (int)(((long)blockIdx.x * blockDim.x + threadIdx.x) >> 5);
    if (w >= NODES) return;
    int lane = threadIdx.x & 31;
    const float4* row = (const float4*)(h + (long)w * 256);
    float4 v0 = row[lane * 2], v1 = row[lane * 2 + 1];
    const float4* pa = (const float4*)asrc;
    const float4* pd = (const float4*)adst;
    float4 a0 = pa[lane * 2], a1 = pa[lane * 2 + 1];
    float4 d0 = pd[lane * 2], d1 = pd[lane * 2 + 1];
    float ss = v0.x*a0.x + v0.y*a0.y + v0.z*a0.z + v0.w*a0.w
             + v1.x*a1.x + v1.y*a1.y + v1.z*a1.z + v1.w*a1.w;
    float sd = v0.x*d0.x + v0.y*d0.y + v0.z*d0.z + v0.w*d0.w
             + v1.x*d1.x + v1.y*d1.y + v1.z*d1.z + v1.w*d1.w;
    #pragma unroll
    for (int o = 4; o; o >>= 1) {
        ss += __shfl_xor_sync(0xffffffffu, ss, o);
        sd += __shfl_xor_sync(0xffffffffu, sd, o);
    }
    if ((lane & 7) == 0) {
        int head = lane >> 3;
        ssrc[w * 4 + head] = ss;
        sdst[w * 4 + head] = sd;
    }
}

// ------------------------- layer-2 scores: warp per node, 1 head ------------
__global__ void scores2_k(const float* __restrict__ h,
                          const float* __restrict__ asrc,
                          const float* __restrict__ adst,
                          float* __restrict__ ssrc, float* __restrict__ sdst)
{
    int w = (int)(((long)blockIdx.x * blockDim.x + threadIdx.x) >> 5);
    if (w >= NODES) return;
    int lane = threadIdx.x & 31;
    const float* row = h + (long)w * 64;
    float v1 = row[lane], v2 = row[lane + 32];
    float ss = v1 * asrc[lane] + v2 * asrc[lane + 32];
    float sd = v1 * adst[lane] + v2 * adst[lane + 32];
    #pragma unroll
    for (int o = 16; o; o >>= 1) {
        ss += __shfl_xor_sync(0xffffffffu, ss, o);
        sd += __shfl_xor_sync(0xffffffffu, sd, o);
    }
    if (lane == 0) { ssrc[w] = ss; sdst[w] = sd; }
}

// -------- layer-1 CSR aggregation: warp per dst node, register acc ----------
__global__ void __launch_bounds__(256) eagg1c_k() {
    int node = (int)(((long)blockIdx.x * blockDim.x + threadIdx.x) >> 5);
    if (node >= NODES) return;
    int lane = threadIdx.x & 31;
    int start = g_rowp[node], deg = g_deg[node];
    float sdv = (lane < 4) ? g_sdst1[node * 4 + lane] : 0.f;
    int ha = lane >> 4, hb = ha + 2;
    float4 accA = make_float4(0.f, 0.f, 0.f, 0.f);
    float4 accB = make_float4(0.f, 0.f, 0.f, 0.f);
    float den = 0.f;
    for (int e = 0; e < deg; e++) {
        int s = g_srt[start + e];
        float ex = 0.f;
        if (lane < 4) {
            float sc = g_ssrc1[s * 4 + lane] + sdv;
            ex = __expf(lrelu(sc));
            den += ex;
        }
        float exa = __shfl_sync(0xffffffffu, ex, ha);
        float exb = __shfl_sync(0xffffffffu, ex, hb);
        const float4* hp = (const float4*)(g_h1lin + (long)s * H1DIM);
        float4 v0 = hp[lane], v1 = hp[lane + 32];
        accA.x += v0.x * exa; accA.y += v0.y * exa;
        accA.z += v0.z * exa; accA.w += v0.w * exa;
        accB.x += v1.x * exb; accB.y += v1.y * exb;
        accB.z += v1.z * exb; accB.w += v1.w * exb;
    }
    float4* ap = (float4*)(g_agg1 + (long)node * H1DIM);
    ap[lane] = accA;
    ap[lane + 32] = accB;
    if (lane < 4) g_den1[node * 4 + lane] = den;
}

// -------- layer-2 CSR aggregation: warp per dst node -------------------------
__global__ void __launch_bounds__(256) eagg2c_k() {
    int node = (int)(((long)blockIdx.x * blockDim.x + threadIdx.x) >> 5);
    if (node >= NODES) return;
    int lane = threadIdx.x & 31;
    int start = g_rowp[node], deg = g_deg[node];
    float sdv = (lane == 0) ? g_sdst2[node] : 0.f;
    float a0 = 0.f, a1 = 0.f, den = 0.f;
    for (int e = 0; e < deg; e++) {
        int s = g_srt[start + e];
        float ex = 0.f;
        if (lane == 0) {
            ex = __expf(lrelu(g_ssrc2[s] + sdv));
            den += ex;
        }
        ex = __shfl_sync(0xffffffffu, ex, 0);
        float2 v = ((const float2*)(g_h2lin + (long)s * HIDC))[lane];
        a0 += v.x * ex; a1 += v.y * ex;
    }
    ((float2*)(g_agg2 + (long)node * HIDC))[lane] = make_float2(a0, a1);
    if (lane == 0) g_den2[node] = den;
}

// ------------------------- per-edge MLP finish: warp per edge ---------------
__global__ void __launch_bounds__(256) edge_k(
    const float* __restrict__ PQ,
    const float* __restrict__ bm1, const float* __restrict__ Wm2,
    const float* __restrict__ bm2, float* __restrict__ out)
{
    long tid = (long)blockIdx.x * blockDim.x + threadIdx.x;
    int w = (int)(tid >> 5);
    if (w >= NEDGE) return;
    int lane = threadIdx.x & 31;
    int s = g_ei[w], d = g_ei[NEDGE + w];
    float2 p = *(const float2*)(PQ + (long)s * 128 + lane * 2);
    float2 q = *(const float2*)(PQ + (long)d * 128 + 64 + lane * 2);
    float2 b = *(const float2*)(bm1 + lane * 2);
    float h0 = fmaxf(p.x + q.x + b.x, 0.f);
    float h1 = fmaxf(p.y + q.y + b.y, 0.f);
    float4 w4 = *(const float4*)(Wm2 + lane * 4);
    float o0 = h0 * w4.x + h1 * w4.z;
    float o1 = h0 * w4.y + h1 * w4.w;
    #pragma unroll
    for (int off = 16; off; off >>= 1) {
        o0 += __shfl_xor_sync(0xffffffffu, o0, off);
        o1 += __shfl_xor_sync(0xffffffffu, o1, off);
    }
    if (lane == 0) {
        float2 r = make_float2(o0 + bm2[0], o1 + bm2[1]);
        *(float2*)(out + (long)w * 2) = r;
    }
}

// ------------------------- launch -------------------------------------------
extern "C" void kernel_launch(void* const* d_in, const int* in_sizes, int n_in,
                              void* d_out, int out_size)
{
    const float* x   = (const float*)d_in[0];
    const void*  eir = d_in[1];
    const float* W1  = (const float*)d_in[2];
    const float* as1 = (const float*)d_in[3];
    const float* ad1 = (const float*)d_in[4];
    const float* b1  = (const float*)d_in[5];
    const float* W2  = (const float*)d_in[6];
    const float* as2 = (const float*)d_in[7];
    const float* ad2 = (const float*)d_in[8];
    const float* b2  = (const float*)d_in[9];
    const float* Wm1 = (const float*)d_in[10];
    const float* bm1 = (const float*)d_in[11];
    const float* Wm2 = (const float*)d_in[12];
    const float* bm2 = (const float*)d_in[13];
    float* out = (float*)d_out;

    void* p;
    cudaGetSymbolAddress(&p, g_h1lin); float* h1lin = (float*)p;
    cudaGetSymbolAddress(&p, g_agg1);  float* agg1  = (float*)p;
    cudaGetSymbolAddress(&p, g_h2lin); float* h2lin = (float*)p;
    cudaGetSymbolAddress(&p, g_agg2);  float* agg2  = (float*)p;
    cudaGetSymbolAddress(&p, g_PQ);    float* PQ    = (float*)p;
    cudaGetSymbolAddress(&p, g_Bc);    float* Bc    = (float*)p;
    cudaGetSymbolAddress(&p, g_ssrc1); float* ssrc1 = (float*)p;
    cudaGetSymbolAddress(&p, g_sdst1); float* sdst1 = (float*)p;
    cudaGetSymbolAddress(&p, g_den1);  float* den1  = (float*)p;
    cudaGetSymbolAddress(&p, g_ssrc2); float* ssrc2 = (float*)p;
    cudaGetSymbolAddress(&p, g_sdst2); float* sdst2 = (float*)p;
    cudaGetSymbolAddress(&p, g_den2);  float* den2  = (float*)p;

    const int MT = (NODES + 127) / 128;   // 391

    detect_k<<<1, 256>>>(eir);
    setup_k<<<(NODES + 255) / 256, 256>>>(Wm1);
    conv_k<<<(2 * NEDGE + 255) / 256, 256>>>(eir);
    scan_k<<<1, 1024>>>();
    scatter_k<<<(AUGE + 255) / 256, 256>>>();

    // ---- layer 1 (4 heads, concat) ----
    gemmt_k<0><<<dim3(MT, H1DIM / 64), 256>>>(
        x, W1, nullptr, nullptr, h1lin, NODES, INC, H1DIM);
    scores1_k<<<(NODES * 32 + 255) / 256, 256>>>(h1lin, as1, ad1, ssrc1, sdst1);
    eagg1c_k<<<(NODES * 32 + 255) / 256, 256>>>();

    // ---- layer 2; relu(agg1/den1 + b1) fused into A-load ----
    gemmt_k<1><<<dim3(MT, 1), 256>>>(
        agg1, W2, b1, den1, h2lin, NODES, H1DIM, HIDC);
    scores2_k<<<(NODES * 32 + 255) / 256, 256>>>(h2lin, as2, ad2, ssrc2, sdst2);
    eagg2c_k<<<(NODES * 32 + 255) / 256, 256>>>();

    // ---- edge MLP, factorized: PQ = (agg2/den2 + b2) @ [Wm1_top | Wm1_bot] ----
    gemmt_k<2><<<dim3(MT, 2), 256>>>(
        agg2, Bc, b2, den2, PQ, NODES, HIDC, 2 * HIDC);
    edge_k<<<(int)(((long)NEDGE * 32 + 255) / 256), 256>>>(PQ, bm1, Wm2, bm2, out);
}

// round 7
// speedup vs baseline: 1.7669x; 1.1949x over previous
#include <cuda_runtime.h>

#define NODES  50000
#define NEDGE  800000
#define AUGE   (NEDGE + NODES)     // 850000
#define INC    128
#define HIDC   64
#define NHEADS 4
#define H1DIM  (NHEADS * HIDC)     // 256
#define NSCAN  ((NODES + 1023) / 1024)   // 49

// ------------------------- scratch (static device memory) -------------------
__device__ float    g_h1lin[(size_t)NODES * H1DIM];
__device__ float    g_agg1 [(size_t)NODES * H1DIM];   // unnormalized
__device__ float    g_h2lin[(size_t)NODES * HIDC];
__device__ float    g_agg2 [(size_t)NODES * HIDC];    // unnormalized
__device__ float    g_PQ   [(size_t)NODES * 2 * HIDC];
__device__ float    g_Bc   [HIDC * 2 * HIDC];
__device__ float    g_ssrc1[NODES * NHEADS];
__device__ float    g_sdst1[NODES * NHEADS];
__device__ float    g_den1 [NODES * NHEADS];
__device__ float    g_ssrc2[NODES];
__device__ float    g_sdst2[NODES];
__device__ float    g_den2 [NODES];
__device__ int      g_ei   [2 * NEDGE];
__device__ int      g_deg  [NODES];
__device__ int      g_rowp [NODES];
__device__ int      g_pos  [NODES];
__device__ int      g_bsum [NSCAN];
__device__ int      g_boff [NSCAN];
__device__ int      g_srt  [AUGE];     // src ids sorted by dst
__device__ int      g_is64;

// ------------------------- helpers ------------------------------------------
__device__ __forceinline__ float lrelu(float x) { return x >= 0.f ? x : 0.2f * x; }
__device__ __forceinline__ unsigned t32(float x) {
    unsigned r; asm("cvt.rna.tf32.f32 %0, %1;" : "=r"(r) : "f"(x)); return r;
}
__device__ __forceinline__ void mma_tf32(float4& d, const unsigned* a,
                                         unsigned b0, unsigned b1) {
    asm("mma.sync.aligned.m16n8k8.row.col.f32.tf32.tf32.f32 "
        "{%0,%1,%2,%3},{%4,%5,%6,%7},{%8,%9},{%0,%1,%2,%3};"
        : "+f"(d.x), "+f"(d.y), "+f"(d.z), "+f"(d.w)
        : "r"(a[0]), "r"(a[1]), "r"(a[2]), "r"(a[3]), "r"(b0), "r"(b1));
}

// ------------------------- edge index dtype detect + normalize --------------
__global__ void detect_k(const void* p) {
    __shared__ int nz;
    if (threadIdx.x == 0) nz = 0;
    __syncthreads();
    const int2* q = (const int2*)p;
    for (int i = threadIdx.x; i < 4096; i += blockDim.x)
        if (q[i].y != 0) nz = 1;
    __syncthreads();
    if (threadIdx.x == 0) g_is64 = (nz == 0) ? 1 : 0;
}
// conv + degree histogram fused (g_deg pre-seeded to 1 for self-loops)
__global__ void conv_k(const void* p) {
    int i = blockIdx.x * blockDim.x + threadIdx.x;
    if (i >= 2 * NEDGE) return;
    long long v = g_is64 ? ((const long long*)p)[i]
                         : (long long)((const int*)p)[i];
    int vi = (int)v;
    g_ei[i] = vi;
    if (i >= NEDGE) atomicAdd(&g_deg[vi], 1);
}

// ------------------------- setup: seed degrees + repack Wm1 -----------------
__global__ void setup_k(const float* __restrict__ Wm1) {
    int i = blockIdx.x * blockDim.x + threadIdx.x;
    if (i < NODES) g_deg[i] = 1;   // self-loop
    if (i < HIDC * 2 * HIDC) {
        int k = i >> 7, j = i & 127;
        g_Bc[i] = (j < HIDC) ? Wm1[k * HIDC + j] : Wm1[(HIDC + k) * HIDC + (j - HIDC)];
    }
}

// ------------------------- hierarchical CSR scan -----------------------------
__global__ void __launch_bounds__(1024) scan1_k() {
    __shared__ int sh[1024];
    int t = threadIdx.x;
    int idx = blockIdx.x * 1024 + t;
    int v = (idx < NODES) ? g_deg[idx] : 0;
    sh[t] = v;
    __syncthreads();
    int acc = v;
    #pragma unroll
    for (int off = 1; off < 1024; off <<= 1) {
        int u = (t >= off) ? sh[t - off] : 0;
        __syncthreads();
        acc += u;
        sh[t] = acc;
        __syncthreads();
    }
    if (idx < NODES) g_rowp[idx] = acc - v;   // exclusive within block
    if (t == 1023) g_bsum[blockIdx.x] = acc;  // block total
}
__global__ void scan2_k() {
    int t = threadIdx.x;          // 64 threads
    int v = (t < NSCAN) ? g_bsum[t] : 0;
    int x = v;
    #pragma unroll
    for (int off = 1; off < 64; off <<= 1) {
        int u = __shfl_up_sync(0xffffffffu, x, off, 32);
        if ((t & 31) >= off) x += u;
    }
    __shared__ int w0;
    if (t == 31) w0 = x;
    __syncthreads();
    if (t >= 32) x += w0;
    if (t < NSCAN) g_boff[t] = x - v;   // exclusive
}
__global__ void __launch_bounds__(1024) scan3_k() {
    int idx = blockIdx.x * 1024 + threadIdx.x;
    if (idx >= NODES) return;
    int r = g_rowp[idx] + g_boff[blockIdx.x];
    g_rowp[idx] = r;
    g_pos[idx]  = r;
}
__global__ void scatter_k() {
    int i = blockIdx.x * blockDim.x + threadIdx.x;
    if (i >= AUGE) return;
    int s, d;
    if (i < NEDGE) { s = g_ei[i]; d = g_ei[NEDGE + i]; } else { s = d = i - NEDGE; }
    int p = atomicAdd(&g_pos[d], 1);
    g_srt[p] = s;
}

// ---------------- tf32 tensor-core GEMM: 128x64 block, BK=32 ----------------
// 8 warps = 4(m) x 2(n); warp tile 32m x 32n; mma m16n8k8.
// AMODE 0: plain A; 1: relu(A/den[r,(k>>6)] + biasA[k]); 2: A/den[r] + biasA[k]
template<int AMODE>
__global__ void __launch_bounds__(256) gemmt_k(
    const float* __restrict__ A, const float* __restrict__ B,
    const float* __restrict__ biasA, const float* __restrict__ den,
    float* __restrict__ C, int M, int K, int Nc)
{
    __shared__ unsigned Asm[4 * 8 * 32 * 4];      // 16KB
    __shared__ unsigned Bsm[2 * 4 * 2 * 32 * 4];  // 8KB
    int t = threadIdx.x;
    int lane = t & 31, warp = t >> 5;
    int wm = warp >> 1, wn = warp & 1;
    int m0 = blockIdx.x * 128, n0 = blockIdx.y * 64;

    float4 acc[2][4];
    #pragma unroll
    for (int i = 0; i < 2; i++)
        #pragma unroll
        for (int j = 0; j < 4; j++) acc[i][j] = make_float4(0.f, 0.f, 0.f, 0.f);

    for (int k0 = 0; k0 < K; k0 += 32) {
        #pragma unroll
        for (int i = t; i < 1024; i += 256) {
            int r = i >> 3;
            int kq = (i & 7) << 2;
            int gr = m0 + r;
            float4 v = make_float4(0.f, 0.f, 0.f, 0.f);
            if (gr < M) {
                v = *(const float4*)(A + (long)gr * K + k0 + kq);
                if (AMODE == 1) {
                    float inv = 1.f / (den[gr * 4 + ((k0 + kq) >> 6)] + 1e-16f);
                    float4 b = *(const float4*)(biasA + k0 + kq);
                    v.x = fmaxf(v.x * inv + b.x, 0.f);
                    v.y = fmaxf(v.y * inv + b.y, 0.f);
                    v.z = fmaxf(v.z * inv + b.z, 0.f);
                    v.w = fmaxf(v.w * inv + b.w, 0.f);
                } else if (AMODE == 2) {
                    float inv = 1.f / (den[gr] + 1e-16f);
                    float4 b = *(const float4*)(biasA + k0 + kq);
                    v.x = v.x * inv + b.x; v.y = v.y * inv + b.y;
                    v.z = v.z * inv + b.z; v.w = v.w * inv + b.w;
                }
            }
            int kstep = kq >> 3;
            int mtile = r >> 4, rr = r & 15;
            int j = (rr >= 8 ? 1 : 0) + ((kq & 4) ? 2 : 0);
            int lane0 = (rr & 7) << 2;
            unsigned* bp = Asm + (((kstep * 8 + mtile) * 32) + lane0) * 4 + j;
            bp[(0 ^ kstep) * 4] = t32(v.x);
            bp[(1 ^ kstep) * 4] = t32(v.y);
            bp[(2 ^ kstep) * 4] = t32(v.z);
            bp[(3 ^ kstep) * 4] = t32(v.w);
        }
        #pragma unroll
        for (int i = t; i < 512; i += 256) {
            int kk = i >> 4;
            int nq = (i & 15) << 2;
            float4 v = *(const float4*)(B + (long)(k0 + kk) * Nc + n0 + nq);
            int kstep = kk >> 3, klo = kk & 3, bsel = ((kk & 7) >= 4);
            unsigned tv[4] = { t32(v.x), t32(v.y), t32(v.z), t32(v.w) };
            #pragma unroll
            for (int c = 0; c < 4; c++) {
                int ng = nq + c;
                int g = ng >> 5, nn = ng & 31, tt = nn >> 3;
                int ln = ((nn & 7) << 2) | klo;
                Bsm[(tt >> 1) * 1024 + (((kstep * 2 + g) * 32) + ln) * 4
                    + (tt & 1) * 2 + bsel] = tv[c];
            }
        }
        __syncthreads();
        #pragma unroll
        for (int kstep = 0; kstep < 4; kstep++) {
            unsigned a[2][4], b[8];
            #pragma unroll
            for (int i = 0; i < 2; i++)
                *(uint4*)a[i] = *(const uint4*)
                    &Asm[(((kstep * 8) + (wm * 2 + i)) * 32 + (lane ^ kstep)) * 4];
            *(uint4*)&b[0] = *(const uint4*)&Bsm[(((kstep * 2 + wn) * 32) + lane) * 4];
            *(uint4*)&b[4] = *(const uint4*)&Bsm[1024 + (((kstep * 2 + wn) * 32) + lane) * 4];
            #pragma unroll
            for (int i = 0; i < 2; i++) {
                mma_tf32(acc[i][0], a[i], b[0], b[1]);
                mma_tf32(acc[i][1], a[i], b[2], b[3]);
                mma_tf32(acc[i][2], a[i], b[4], b[5]);
                mma_tf32(acc[i][3], a[i], b[6], b[7]);
            }
        }
        __syncthreads();
    }
    int mw = m0 + wm * 32;
    int nw = n0 + wn * 32;
    #pragma unroll
    for (int i = 0; i < 2; i++) {
        int rlo = mw + i * 16 + (lane >> 2);
        int rhi = rlo + 8;
        #pragma unroll
        for (int tt = 0; tt < 4; tt++) {
            int col = nw + tt * 8 + (lane & 3) * 2;
            if (rlo < M)
                *(float2*)(C + (long)rlo * Nc + col) = make_float2(acc[i][tt].x, acc[i][tt].y);
            if (rhi < M)
                *(float2*)(C + (long)rhi * Nc + col) = make_float2(acc[i][tt].z, acc[i][tt].w);
        }
    }
}

// ------------------------- layer-1 scores: warp per node, 4 heads -----------
__global__ void scores1_k(const float* __restrict__ h,
                          const float* __restrict__ asrc,
                          const float* __restrict__ adst,
                          float* __restrict__ ssrc, float* __restrict__ sdst)
{
    int w = (int)(((long)blockIdx.x * blockDim.x + threadIdx.x) >> 5);
    if (w >= NODES) return;
    int lane = threadIdx.x & 31;
    const float4* row = (const float4*)(h + (long)w * 256);
    float4 v0 = row[lane * 2], v1 = row[lane * 2 + 1];
    const float4* pa = (const float4*)asrc;
    const float4* pd = (const float4*)adst;
    float4 a0 = pa[lane * 2], a1 = pa[lane * 2 + 1];
    float4 d0 = pd[lane * 2], d1 = pd[lane * 2 + 1];
    float ss = v0.x*a0.x + v0.y*a0.y + v0.z*a0.z + v0.w*a0.w
             + v1.x*a1.x + v1.y*a1.y + v1.z*a1.z + v1.w*a1.w;
    float sd = v0.x*d0.x + v0.y*d0.y + v0.z*d0.z + v0.w*d0.w
             + v1.x*d1.x + v1.y*d1.y + v1.z*d1.z + v1.w*d1.w;
    #pragma unroll
    for (int o = 4; o; o >>= 1) {
        ss += __shfl_xor_sync(0xffffffffu, ss, o);
        sd += __shfl_xor_sync(0xffffffffu, sd, o);
    }
    if ((lane & 7) == 0) {
        int head = lane >> 3;
        ssrc[w * 4 + head] = ss;
        sdst[w * 4 + head] = sd;
    }
}

// ------------------------- layer-2 scores: warp per node, 1 head ------------
__global__ void scores2_k(const float* __restrict__ h,
                          const float* __restrict__ asrc,
                          const float* __restrict__ adst,
                          float* __restrict__ ssrc, float* __restrict__ sdst)
{
    int w = (int)(((long)blockIdx.x * blockDim.x + threadIdx.x) >> 5);
    if (w >= NODES) return;
    int lane = threadIdx.x & 31;
    const float* row = h + (long)w * 64;
    float v1 = row[lane], v2 = row[lane + 32];
    float ss = v1 * asrc[lane] + v2 * asrc[lane + 32];
    float sd = v1 * adst[lane] + v2 * adst[lane + 32];
    #pragma unroll
    for (int o = 16; o; o >>= 1) {
        ss += __shfl_xor_sync(0xffffffffu, ss, o);
        sd += __shfl_xor_sync(0xffffffffu, sd, o);
    }
    if (lane == 0) { ssrc[w] = ss; sdst[w] = sd; }
}

// -------- layer-1 CSR aggregation: warp per dst node, register acc ----------
__global__ void __launch_bounds__(256) eagg1c_k() {
    int node = (int)(((long)blockIdx.x * blockDim.x + threadIdx.x) >> 5);
    if (node >= NODES) return;
    int lane = threadIdx.x & 31;
    int start = g_rowp[node], deg = g_deg[node];
    float sdv = (lane < 4) ? g_sdst1[node * 4 + lane] : 0.f;
    int ha = lane >> 4, hb = ha + 2;
    float4 accA = make_float4(0.f, 0.f, 0.f, 0.f);
    float4 accB = make_float4(0.f, 0.f, 0.f, 0.f);
    float den = 0.f;
    for (int e = 0; e < deg; e++) {
        int s = g_srt[start + e];
        float ex = 0.f;
        if (lane < 4) {
            float sc = g_ssrc1[s * 4 + lane] + sdv;
            ex = __expf(lrelu(sc));
            den += ex;
        }
        float exa = __shfl_sync(0xffffffffu, ex, ha);
        float exb = __shfl_sync(0xffffffffu, ex, hb);
        const float4* hp = (const float4*)(g_h1lin + (long)s * H1DIM);
        float4 v0 = hp[lane], v1 = hp[lane + 32];
        accA.x += v0.x * exa; accA.y += v0.y * exa;
        accA.z += v0.z * exa; accA.w += v0.w * exa;
        accB.x += v1.x * exb; accB.y += v1.y * exb;
        accB.z += v1.z * exb; accB.w += v1.w * exb;
    }
    float4* ap = (float4*)(g_agg1 + (long)node * H1DIM);
    ap[lane] = accA;
    ap[lane + 32] = accB;
    if (lane < 4) g_den1[node * 4 + lane] = den;
}

// -------- layer-2 CSR aggregation: warp per dst node -------------------------
__global__ void __launch_bounds__(256) eagg2c_k() {
    int node = (int)(((long)blockIdx.x * blockDim.x + threadIdx.x) >> 5);
    if (node >= NODES) return;
    int lane = threadIdx.x & 31;
    int start = g_rowp[node], deg = g_deg[node];
    float sdv = (lane == 0) ? g_sdst2[node] : 0.f;
    float a0 = 0.f, a1 = 0.f, den = 0.f;
    for (int e = 0; e < deg; e++) {
        int s = g_srt[start + e];
        float ex = 0.f;
        if (lane == 0) {
            ex = __expf(lrelu(g_ssrc2[s] + sdv));
            den += ex;
        }
        ex = __shfl_sync(0xffffffffu, ex, 0);
        float2 v = ((const float2*)(g_h2lin + (long)s * HIDC))[lane];
        a0 += v.x * ex; a1 += v.y * ex;
    }
    ((float2*)(g_agg2 + (long)node * HIDC))[lane] = make_float2(a0, a1);
    if (lane == 0) g_den2[node] = den;
}

// ------------------------- per-edge MLP finish: warp per edge ---------------
__global__ void __launch_bounds__(256) edge_k(
    const float* __restrict__ PQ,
    const float* __restrict__ bm1, const float* __restrict__ Wm2,
    const float* __restrict__ bm2, float* __restrict__ out)
{
    long tid = (long)blockIdx.x * blockDim.x + threadIdx.x;
    int w = (int)(tid >> 5);
    if (w >= NEDGE) return;
    int lane = threadIdx.x & 31;
    int s = g_ei[w], d = g_ei[NEDGE + w];
    float2 p = *(const float2*)(PQ + (long)s * 128 + lane * 2);
    float2 q = *(const float2*)(PQ + (long)d * 128 + 64 + lane * 2);
    float2 b = *(const float2*)(bm1 + lane * 2);
    float h0 = fmaxf(p.x + q.x + b.x, 0.f);
    float h1 = fmaxf(p.y + q.y + b.y, 0.f);
    float4 w4 = *(const float4*)(Wm2 + lane * 4);
    float o0 = h0 * w4.x + h1 * w4.z;
    float o1 = h0 * w4.y + h1 * w4.w;
    #pragma unroll
    for (int off = 16; off; off >>= 1) {
        o0 += __shfl_xor_sync(0xffffffffu, o0, off);
        o1 += __shfl_xor_sync(0xffffffffu, o1, off);
    }
    if (lane == 0) {
        float2 r = make_float2(o0 + bm2[0], o1 + bm2[1]);
        *(float2*)(out + (long)w * 2) = r;
    }
}

// ------------------------- launch -------------------------------------------
extern "C" void kernel_launch(void* const* d_in, const int* in_sizes, int n_in,
                              void* d_out, int out_size)
{
    const float* x   = (const float*)d_in[0];
    const void*  eir = d_in[1];
    const float* W1  = (const float*)d_in[2];
    const float* as1 = (const float*)d_in[3];
    const float* ad1 = (const float*)d_in[4];
    const float* b1  = (const float*)d_in[5];
    const float* W2  = (const float*)d_in[6];
    const float* as2 = (const float*)d_in[7];
    const float* ad2 = (const float*)d_in[8];
    const float* b2  = (const float*)d_in[9];
    const float* Wm1 = (const float*)d_in[10];
    const float* bm1 = (const float*)d_in[11];
    const float* Wm2 = (const float*)d_in[12];
    const float* bm2 = (const float*)d_in[13];
    float* out = (float*)d_out;

    void* p;
    cudaGetSymbolAddress(&p, g_h1lin); float* h1lin = (float*)p;
    cudaGetSymbolAddress(&p, g_agg1);  float* agg1  = (float*)p;
    cudaGetSymbolAddress(&p, g_h2lin); float* h2lin = (float*)p;
    cudaGetSymbolAddress(&p, g_agg2);  float* agg2  = (float*)p;
    cudaGetSymbolAddress(&p, g_PQ);    float* PQ    = (float*)p;
    cudaGetSymbolAddress(&p, g_Bc);    float* Bc    = (float*)p;
    cudaGetSymbolAddress(&p, g_ssrc1); float* ssrc1 = (float*)p;
    cudaGetSymbolAddress(&p, g_sdst1); float* sdst1 = (float*)p;
    cudaGetSymbolAddress(&p, g_den1);  float* den1  = (float*)p;
    cudaGetSymbolAddress(&p, g_ssrc2); float* ssrc2 = (float*)p;
    cudaGetSymbolAddress(&p, g_sdst2); float* sdst2 = (float*)p;
    cudaGetSymbolAddress(&p, g_den2);  float* den2  = (float*)p;

    const int MT = (NODES + 127) / 128;   // 391

    detect_k<<<1, 256>>>(eir);
    setup_k<<<(NODES + 255) / 256, 256>>>(Wm1);
    conv_k<<<(2 * NEDGE + 255) / 256, 256>>>(eir);
    scan1_k<<<NSCAN, 1024>>>();
    scan2_k<<<1, 64>>>();
    scan3_k<<<NSCAN, 1024>>>();
    scatter_k<<<(AUGE + 255) / 256, 256>>>();

    // ---- layer 1 (4 heads, concat) ----
    gemmt_k<0><<<dim3(MT, H1DIM / 64), 256>>>(
        x, W1, nullptr, nullptr, h1lin, NODES, INC, H1DIM);
    scores1_k<<<(NODES * 32 + 255) / 256, 256>>>(h1lin, as1, ad1, ssrc1, sdst1);
    eagg1c_k<<<(NODES * 32 + 255) / 256, 256>>>();

    // ---- layer 2; relu(agg1/den1 + b1) fused into A-load ----
    gemmt_k<1><<<dim3(MT, 1), 256>>>(
        agg1, W2, b1, den1, h2lin, NODES, H1DIM, HIDC);
    scores2_k<<<(NODES * 32 + 255) / 256, 256>>>(h2lin, as2, ad2, ssrc2, sdst2);
    eagg2c_k<<<(NODES * 32 + 255) / 256, 256>>>();

    // ---- edge MLP, factorized: PQ = (agg2/den2 + b2) @ [Wm1_top | Wm1_bot] ----
    gemmt_k<2><<<dim3(MT, 2), 256>>>(
        agg2, Bc, b2, den2, PQ, NODES, HIDC, 2 * HIDC);
    edge_k<<<(int)(((long)NEDGE * 32 + 255) / 256), 256>>>(PQ, bm1, Wm2, bm2, out);
}

// round 8
// speedup vs baseline: 1.8782x; 1.0630x over previous
#include <cuda_runtime.h>
#include <cuda_fp16.h>

#define NODES  50000
#define NEDGE  800000
#define AUGE   (NEDGE + NODES)     // 850000
#define INC    128
#define HIDC   64
#define NHEADS 4
#define H1DIM  (NHEADS * HIDC)     // 256
#define NSCAN  ((NODES + 1023) / 1024)   // 49

// ------------------------- scratch (static device memory) -------------------
__device__ __half   g_h1h  [(size_t)NODES * H1DIM];   // layer-1 features (fp16)
__device__ float    g_agg1 [(size_t)NODES * H1DIM];   // unnormalized
__device__ float    g_h2lin[(size_t)NODES * HIDC];
__device__ float    g_agg2 [(size_t)NODES * HIDC];    // unnormalized
__device__ __half   g_PQh  [(size_t)NODES * 2 * HIDC];// P|Q (fp16)
__device__ float    g_Bc   [HIDC * 2 * HIDC];
__device__ float    g_ssrc1[NODES * NHEADS];
__device__ float    g_sdst1[NODES * NHEADS];
__device__ float    g_den1 [NODES * NHEADS];
__device__ float    g_ssrc2[NODES];
__device__ float    g_sdst2[NODES];
__device__ float    g_den2 [NODES];
__device__ int      g_ei   [2 * NEDGE];
__device__ int      g_deg  [NODES];
__device__ int      g_rowp [NODES];
__device__ int      g_pos  [NODES];
__device__ int      g_bsum [NSCAN];
__device__ int      g_boff [NSCAN];
__device__ int      g_srt  [AUGE];
__device__ int      g_is64;

// ------------------------- helpers ------------------------------------------
__device__ __forceinline__ float lrelu(float x) { return x >= 0.f ? x : 0.2f * x; }
__device__ __forceinline__ unsigned t32(float x) {
    unsigned r; asm("cvt.rna.tf32.f32 %0, %1;" : "=r"(r) : "f"(x)); return r;
}
__device__ __forceinline__ void mma_tf32(float4& d, const unsigned* a,
                                         unsigned b0, unsigned b1) {
    asm("mma.sync.aligned.m16n8k8.row.col.f32.tf32.tf32.f32 "
        "{%0,%1,%2,%3},{%4,%5,%6,%7},{%8,%9},{%0,%1,%2,%3};"
        : "+f"(d.x), "+f"(d.y), "+f"(d.z), "+f"(d.w)
        : "r"(a[0]), "r"(a[1]), "r"(a[2]), "r"(a[3]), "r"(b0), "r"(b1));
}

// ------------------------- edge index dtype detect + normalize --------------
__global__ void detect_k(const void* p) {
    __shared__ int nz;
    if (threadIdx.x == 0) nz = 0;
    __syncthreads();
    const int2* q = (const int2*)p;
    for (int i = threadIdx.x; i < 4096; i += blockDim.x)
        if (q[i].y != 0) nz = 1;
    __syncthreads();
    if (threadIdx.x == 0) g_is64 = (nz == 0) ? 1 : 0;
}
__global__ void conv_k(const void* p) {
    int i = blockIdx.x * blockDim.x + threadIdx.x;
    if (i >= 2 * NEDGE) return;
    long long v = g_is64 ? ((const long long*)p)[i]
                         : (long long)((const int*)p)[i];
    int vi = (int)v;
    g_ei[i] = vi;
    if (i >= NEDGE) atomicAdd(&g_deg[vi], 1);
}

// ------------------------- setup: seed degrees + repack Wm1 -----------------
__global__ void setup_k(const float* __restrict__ Wm1) {
    int i = blockIdx.x * blockDim.x + threadIdx.x;
    if (i < NODES) g_deg[i] = 1;
    if (i < HIDC * 2 * HIDC) {
        int k = i >> 7, j = i & 127;
        g_Bc[i] = (j < HIDC) ? Wm1[k * HIDC + j] : Wm1[(HIDC + k) * HIDC + (j - HIDC)];
    }
}

// ------------------------- hierarchical CSR scan -----------------------------
__global__ void __launch_bounds__(1024) scan1_k() {
    __shared__ int sh[1024];
    int t = threadIdx.x;
    int idx = blockIdx.x * 1024 + t;
    int v = (idx < NODES) ? g_deg[idx] : 0;
    sh[t] = v;
    __syncthreads();
    int acc = v;
    #pragma unroll
    for (int off = 1; off < 1024; off <<= 1) {
        int u = (t >= off) ? sh[t - off] : 0;
        __syncthreads();
        acc += u;
        sh[t] = acc;
        __syncthreads();
    }
    if (idx < NODES) g_rowp[idx] = acc - v;
    if (t == 1023) g_bsum[blockIdx.x] = acc;
}
__global__ void scan2_k() {
    int t = threadIdx.x;
    int v = (t < NSCAN) ? g_bsum[t] : 0;
    int x = v;
    #pragma unroll
    for (int off = 1; off < 64; off <<= 1) {
        int u = __shfl_up_sync(0xffffffffu, x, off, 32);
        if ((t & 31) >= off) x += u;
    }
    __shared__ int w0;
    if (t == 31) w0 = x;
    __syncthreads();
    if (t >= 32) x += w0;
    if (t < NSCAN) g_boff[t] = x - v;
}
__global__ void __launch_bounds__(1024) scan3_k() {
    int idx = blockIdx.x * 1024 + threadIdx.x;
    if (idx >= NODES) return;
    int r = g_rowp[idx] + g_boff[blockIdx.x];
    g_rowp[idx] = r;
    g_pos[idx]  = r;
}
__global__ void scatter_k() {
    int i = blockIdx.x * blockDim.x + threadIdx.x;
    if (i >= AUGE) return;
    int s, d;
    if (i < NEDGE) { s = g_ei[i]; d = g_ei[NEDGE + i]; } else { s = d = i - NEDGE; }
    int p = atomicAdd(&g_pos[d], 1);
    g_srt[p] = s;
}

// ---------------- tf32 tensor-core GEMM: 128x64 block, BK=32 ----------------
// AMODE 0: plain A; 1: relu(A/den[r,(k>>6)] + biasA[k]); 2: A/den[r] + biasA[k]
// CHALF 0: C fp32; 1: C fp16
template<int AMODE, int CHALF>
__global__ void __launch_bounds__(256) gemmt_k(
    const float* __restrict__ A, const float* __restrict__ B,
    const float* __restrict__ biasA, const float* __restrict__ den,
    void* __restrict__ Cp, int M, int K, int Nc)
{
    __shared__ unsigned Asm[4 * 8 * 32 * 4];      // 16KB
    __shared__ unsigned Bsm[2 * 4 * 2 * 32 * 4];  // 8KB
    int t = threadIdx.x;
    int lane = t & 31, warp = t >> 5;
    int wm = warp >> 1, wn = warp & 1;
    int m0 = blockIdx.x * 128, n0 = blockIdx.y * 64;

    float4 acc[2][4];
    #pragma unroll
    for (int i = 0; i < 2; i++)
        #pragma unroll
        for (int j = 0; j < 4; j++) acc[i][j] = make_float4(0.f, 0.f, 0.f, 0.f);

    for (int k0 = 0; k0 < K; k0 += 32) {
        #pragma unroll
        for (int i = t; i < 1024; i += 256) {
            int r = i >> 3;
            int kq = (i & 7) << 2;
            int gr = m0 + r;
            float4 v = make_float4(0.f, 0.f, 0.f, 0.f);
            if (gr < M) {
                v = *(const float4*)(A + (long)gr * K + k0 + kq);
                if (AMODE == 1) {
                    float inv = 1.f / (den[gr * 4 + ((k0 + kq) >> 6)] + 1e-16f);
                    float4 b = *(const float4*)(biasA + k0 + kq);
                    v.x = fmaxf(v.x * inv + b.x, 0.f);
                    v.y = fmaxf(v.y * inv + b.y, 0.f);
                    v.z = fmaxf(v.z * inv + b.z, 0.f);
                    v.w = fmaxf(v.w * inv + b.w, 0.f);
                } else if (AMODE == 2) {
                    float inv = 1.f / (den[gr] + 1e-16f);
                    float4 b = *(const float4*)(biasA + k0 + kq);
                    v.x = v.x * inv + b.x; v.y = v.y * inv + b.y;
                    v.z = v.z * inv + b.z; v.w = v.w * inv + b.w;
                }
            }
            int kstep = kq >> 3;
            int mtile = r >> 4, rr = r & 15;
            int j = (rr >= 8 ? 1 : 0) + ((kq & 4) ? 2 : 0);
            int lane0 = (rr & 7) << 2;
            unsigned* bp = Asm + (((kstep * 8 + mtile) * 32) + lane0) * 4 + j;
            bp[(0 ^ kstep) * 4] = t32(v.x);
            bp[(1 ^ kstep) * 4] = t32(v.y);
            bp[(2 ^ kstep) * 4] = t32(v.z);
            bp[(3 ^ kstep) * 4] = t32(v.w);
        }
        #pragma unroll
        for (int i = t; i < 512; i += 256) {
            int kk = i >> 4;
            int nq = (i & 15) << 2;
            float4 v = *(const float4*)(B + (long)(k0 + kk) * Nc + n0 + nq);
            int kstep = kk >> 3, klo = kk & 3, bsel = ((kk & 7) >= 4);
            unsigned tv[4] = { t32(v.x), t32(v.y), t32(v.z), t32(v.w) };
            #pragma unroll
            for (int c = 0; c < 4; c++) {
                int ng = nq + c;
                int g = ng >> 5, nn = ng & 31, tt = nn >> 3;
                int ln = ((nn & 7) << 2) | klo;
                Bsm[(tt >> 1) * 1024 + (((kstep * 2 + g) * 32) + ln) * 4
                    + (tt & 1) * 2 + bsel] = tv[c];
            }
        }
        __syncthreads();
        #pragma unroll
        for (int kstep = 0; kstep < 4; kstep++) {
            unsigned a[2][4], b[8];
            #pragma unroll
            for (int i = 0; i < 2; i++)
                *(uint4*)a[i] = *(const uint4*)
                    &Asm[(((kstep * 8) + (wm * 2 + i)) * 32 + (lane ^ kstep)) * 4];
            *(uint4*)&b[0] = *(const uint4*)&Bsm[(((kstep * 2 + wn) * 32) + lane) * 4];
            *(uint4*)&b[4] = *(const uint4*)&Bsm[1024 + (((kstep * 2 + wn) * 32) + lane) * 4];
            #pragma unroll
            for (int i = 0; i < 2; i++) {
                mma_tf32(acc[i][0], a[i], b[0], b[1]);
                mma_tf32(acc[i][1], a[i], b[2], b[3]);
                mma_tf32(acc[i][2], a[i], b[4], b[5]);
                mma_tf32(acc[i][3], a[i], b[6], b[7]);
            }
        }
        __syncthreads();
    }
    int mw = m0 + wm * 32;
    int nw = n0 + wn * 32;
    #pragma unroll
    for (int i = 0; i < 2; i++) {
        int rlo = mw + i * 16 + (lane >> 2);
        int rhi = rlo + 8;
        #pragma unroll
        for (int tt = 0; tt < 4; tt++) {
            int col = nw + tt * 8 + (lane & 3) * 2;
            if (CHALF) {
                __half* C = (__half*)Cp;
                if (rlo < M)
                    *(__half2*)(C + (long)rlo * Nc + col) =
                        __floats2half2_rn(acc[i][tt].x, acc[i][tt].y);
                if (rhi < M)
                    *(__half2*)(C + (long)rhi * Nc + col) =
                        __floats2half2_rn(acc[i][tt].z, acc[i][tt].w);
            } else {
                float* C = (float*)Cp;
                if (rlo < M)
                    *(float2*)(C + (long)rlo * Nc + col) = make_float2(acc[i][tt].x, acc[i][tt].y);
                if (rhi < M)
                    *(float2*)(C + (long)rhi * Nc + col) = make_float2(acc[i][tt].z, acc[i][tt].w);
            }
        }
    }
}

// ------------------------- layer-1 scores: warp per node (fp16 rows) --------
__global__ void scores1_k(const float* __restrict__ asrc,
                          const float* __restrict__ adst,
                          float* __restrict__ ssrc, float* __restrict__ sdst)
{
    int w = (int)(((long)blockIdx.x * blockDim.x + threadIdx.x) >> 5);
    if (w >= NODES) return;
    int lane = threadIdx.x & 31;
    // lane owns 8 contiguous cols [8*lane, 8*lane+8), all in head lane>>3
    uint4 u = *(const uint4*)(g_h1h + (long)w * 256 + lane * 8);
    __half2 h0 = *(__half2*)&u.x, h1 = *(__half2*)&u.y;
    __half2 h2 = *(__half2*)&u.z, h3 = *(__half2*)&u.w;
    float2 f0 = __half22float2(h0), f1 = __half22float2(h1);
    float2 f2 = __half22float2(h2), f3 = __half22float2(h3);
    int head = lane >> 3;
    int cbase = head * 64 + ((lane * 8) & 63);
    float4 a0 = *(const float4*)(asrc + cbase);
    float4 a1 = *(const float4*)(asrc + cbase + 4);
    float4 d0 = *(const float4*)(adst + cbase);
    float4 d1 = *(const float4*)(adst + cbase + 4);
    float ss = f0.x*a0.x + f0.y*a0.y + f1.x*a0.z + f1.y*a0.w
             + f2.x*a1.x + f2.y*a1.y + f3.x*a1.z + f3.y*a1.w;
    float sd = f0.x*d0.x + f0.y*d0.y + f1.x*d0.z + f1.y*d0.w
             + f2.x*d1.x + f2.y*d1.y + f3.x*d1.z + f3.y*d1.w;
    #pragma unroll
    for (int o = 4; o; o >>= 1) {
        ss += __shfl_xor_sync(0xffffffffu, ss, o);
        sd += __shfl_xor_sync(0xffffffffu, sd, o);
    }
    if ((lane & 7) == 0) {
        ssrc[w * 4 + head] = ss;
        sdst[w * 4 + head] = sd;
    }
}

// ------------------------- layer-2 scores: warp per node, 1 head ------------
__global__ void scores2_k(const float* __restrict__ h,
                          const float* __restrict__ asrc,
                          const float* __restrict__ adst,
                          float* __restrict__ ssrc, float* __restrict__ sdst)
{
    int w = (int)(((long)blockIdx.x * blockDim.x + threadIdx.x) >> 5);
    if (w >= NODES) return;
    int lane = threadIdx.x & 31;
    const float* row = h + (long)w * 64;
    float v1 = row[lane], v2 = row[lane + 32];
    float ss = v1 * asrc[lane] + v2 * asrc[lane + 32];
    float sd = v1 * adst[lane] + v2 * adst[lane + 32];
    #pragma unroll
    for (int o = 16; o; o >>= 1) {
        ss += __shfl_xor_sync(0xffffffffu, ss, o);
        sd += __shfl_xor_sync(0xffffffffu, sd, o);
    }
    if (lane == 0) { ssrc[w] = ss; sdst[w] = sd; }
}

// -------- layer-1 CSR aggregation: warp per dst node, fp16 gather -----------
__global__ void __launch_bounds__(256) eagg1c_k() {
    int node = (int)(((long)blockIdx.x * blockDim.x + threadIdx.x) >> 5);
    if (node >= NODES) return;
    int lane = threadIdx.x & 31;
    int start = g_rowp[node], deg = g_deg[node];
    float sdv = (lane < 4) ? g_sdst1[node * 4 + lane] : 0.f;
    int head = lane >> 3;     // lane's 8 cols all belong to this head
    float acc[8] = {};
    float den = 0.f;
    for (int e = 0; e < deg; e++) {
        int s = g_srt[start + e];
        float ex = 0.f;
        if (lane < 4) {
            float sc = g_ssrc1[s * 4 + lane] + sdv;
            ex = __expf(lrelu(sc));
            den += ex;
        }
        float exv = __shfl_sync(0xffffffffu, ex, head);
        uint4 u = *(const uint4*)(g_h1h + (long)s * 256 + lane * 8);
        float2 f0 = __half22float2(*(__half2*)&u.x);
        float2 f1 = __half22float2(*(__half2*)&u.y);
        float2 f2 = __half22float2(*(__half2*)&u.z);
        float2 f3 = __half22float2(*(__half2*)&u.w);
        acc[0] += f0.x * exv; acc[1] += f0.y * exv;
        acc[2] += f1.x * exv; acc[3] += f1.y * exv;
        acc[4] += f2.x * exv; acc[5] += f2.y * exv;
        acc[6] += f3.x * exv; acc[7] += f3.y * exv;
    }
    float* ap = g_agg1 + (long)node * H1DIM + lane * 8;
    *(float4*)ap       = make_float4(acc[0], acc[1], acc[2], acc[3]);
    *(float4*)(ap + 4) = make_float4(acc[4], acc[5], acc[6], acc[7]);
    if (lane < 4) g_den1[node * 4 + lane] = den;
}

// -------- layer-2 CSR aggregation: warp per dst node -------------------------
__global__ void __launch_bounds__(256) eagg2c_k() {
    int node = (int)(((long)blockIdx.x * blockDim.x + threadIdx.x) >> 5);
    if (node >= NODES) return;
    int lane = threadIdx.x & 31;
    int start = g_rowp[node], deg = g_deg[node];
    float sdv = (lane == 0) ? g_sdst2[node] : 0.f;
    float a0 = 0.f, a1 = 0.f, den = 0.f;
    for (int e = 0; e < deg; e++) {
        int s = g_srt[start + e];
        float ex = 0.f;
        if (lane == 0) {
            ex = __expf(lrelu(g_ssrc2[s] + sdv));
            den += ex;
        }
        ex = __shfl_sync(0xffffffffu, ex, 0);
        float2 v = ((const float2*)(g_h2lin + (long)s * HIDC))[lane];
        a0 += v.x * ex; a1 += v.y * ex;
    }
    ((float2*)(g_agg2 + (long)node * HIDC))[lane] = make_float2(a0, a1);
    if (lane == 0) g_den2[node] = den;
}

// ------------------------- per-edge MLP finish (fp16 PQ gather) -------------
__global__ void __launch_bounds__(256) edge_k(
    const float* __restrict__ bm1, const float* __restrict__ Wm2,
    const float* __restrict__ bm2, float* __restrict__ out)
{
    long tid = (long)blockIdx.x * blockDim.x + threadIdx.x;
    int w = (int)(tid >> 5);
    if (w >= NEDGE) return;
    int lane = threadIdx.x & 31;
    int s = g_ei[w], d = g_ei[NEDGE + w];
    float2 p = __half22float2(*(const __half2*)(g_PQh + (long)s * 128 + lane * 2));
    float2 q = __half22float2(*(const __half2*)(g_PQh + (long)d * 128 + 64 + lane * 2));
    float2 b = *(const float2*)(bm1 + lane * 2);
    float h0 = fmaxf(p.x + q.x + b.x, 0.f);
    float h1 = fmaxf(p.y + q.y + b.y, 0.f);
    float4 w4 = *(const float4*)(Wm2 + lane * 4);
    float o0 = h0 * w4.x + h1 * w4.z;
    float o1 = h0 * w4.y + h1 * w4.w;
    #pragma unroll
    for (int off = 16; off; off >>= 1) {
        o0 += __shfl_xor_sync(0xffffffffu, o0, off);
        o1 += __shfl_xor_sync(0xffffffffu, o1, off);
    }
    if (lane == 0) {
        float2 r = make_float2(o0 + bm2[0], o1 + bm2[1]);
        *(float2*)(out + (long)w * 2) = r;
    }
}

// ------------------------- launch -------------------------------------------
extern "C" void kernel_launch(void* const* d_in, const int* in_sizes, int n_in,
                              void* d_out, int out_size)
{
    const float* x   = (const float*)d_in[0];
    const void*  eir = d_in[1];
    const float* W1  = (const float*)d_in[2];
    const float* as1 = (const float*)d_in[3];
    const float* ad1 = (const float*)d_in[4];
    const float* b1  = (const float*)d_in[5];
    const float* W2  = (const float*)d_in[6];
    const float* as2 = (const float*)d_in[7];
    const float* ad2 = (const float*)d_in[8];
    const float* b2  = (const float*)d_in[9];
    const float* Wm1 = (const float*)d_in[10];
    const float* bm1 = (const float*)d_in[11];
    const float* Wm2 = (const float*)d_in[12];
    const float* bm2 = (const float*)d_in[13];
    float* out = (float*)d_out;

    void* p;
    cudaGetSymbolAddress(&p, g_h1h);   void*  h1h   = p;
    cudaGetSymbolAddress(&p, g_agg1);  float* agg1  = (float*)p;
    cudaGetSymbolAddress(&p, g_h2lin); float* h2lin = (float*)p;
    cudaGetSymbolAddress(&p, g_agg2);  float* agg2  = (float*)p;
    cudaGetSymbolAddress(&p, g_PQh);   void*  PQh   = p;
    cudaGetSymbolAddress(&p, g_Bc);    float* Bc    = (float*)p;
    cudaGetSymbolAddress(&p, g_ssrc1); float* ssrc1 = (float*)p;
    cudaGetSymbolAddress(&p, g_sdst1); float* sdst1 = (float*)p;
    cudaGetSymbolAddress(&p, g_den1);  float* den1  = (float*)p;
    cudaGetSymbolAddress(&p, g_ssrc2); float* ssrc2 = (float*)p;
    cudaGetSymbolAddress(&p, g_sdst2); float* sdst2 = (float*)p;
    cudaGetSymbolAddress(&p, g_den2);  float* den2  = (float*)p;

    const int MT = (NODES + 127) / 128;   // 391

    detect_k<<<1, 256>>>(eir);
    setup_k<<<(NODES + 255) / 256, 256>>>(Wm1);
    conv_k<<<(2 * NEDGE + 255) / 256, 256>>>(eir);
    scan1_k<<<NSCAN, 1024>>>();
    scan2_k<<<1, 64>>>();
    scan3_k<<<NSCAN, 1024>>>();
    scatter_k<<<(AUGE + 255) / 256, 256>>>();

    // ---- layer 1 (4 heads, concat); C stored fp16 ----
    gemmt_k<0, 1><<<dim3(MT, H1DIM / 64), 256>>>(
        x, W1, nullptr, nullptr, h1h, NODES, INC, H1DIM);
    scores1_k<<<(NODES * 32 + 255) / 256, 256>>>(as1, ad1, ssrc1, sdst1);
    eagg1c_k<<<(NODES * 32 + 255) / 256, 256>>>();

    // ---- layer 2; relu(agg1/den1 + b1) fused into A-load ----
    gemmt_k<1, 0><<<dim3(MT, 1), 256>>>(
        agg1, W2, b1, den1, h2lin, NODES, H1DIM, HIDC);
    scores2_k<<<(NODES * 32 + 255) / 256, 256>>>(h2lin, as2, ad2, ssrc2, sdst2);
    eagg2c_k<<<(NODES * 32 + 255) / 256, 256>>>();

    // ---- edge MLP, factorized; PQ stored fp16 ----
    gemmt_k<2, 1><<<dim3(MT, 2), 256>>>(
        agg2, Bc, b2, den2, PQh, NODES, HIDC, 2 * HIDC);
    edge_k<<<(int)(((long)NEDGE * 32 + 255) / 256), 256>>>(bm1, Wm2, bm2, out);
}

// round 10
// speedup vs baseline: 2.0823x; 1.1087x over previous
#include <cuda_runtime.h>
#include <cuda_fp16.h>

#define NODES  50000
#define NEDGE  800000
#define AUGE   (NEDGE + NODES)     // 850000
#define INC    128
#define HIDC   64
#define NHEADS 4
#define H1DIM  (NHEADS * HIDC)     // 256
#define NSCAN  ((NODES + 1023) / 1024)   // 49

// ------------------------- scratch (static device memory) -------------------
__device__ __half   g_h1h  [(size_t)NODES * H1DIM];
__device__ float    g_agg1 [(size_t)NODES * H1DIM];
__device__ float    g_h2lin[(size_t)NODES * HIDC];
__device__ float    g_agg2 [(size_t)NODES * HIDC];
__device__ __half   g_PQh  [(size_t)NODES * 2 * HIDC];
__device__ float    g_Bc   [HIDC * 2 * HIDC];
__device__ float    g_ssrc1[NODES * NHEADS];
__device__ float    g_sdst1[NODES * NHEADS];
__device__ float    g_den1 [NODES * NHEADS];
__device__ float    g_ssrc2[NODES];
__device__ float    g_sdst2[NODES];
__device__ float    g_den2 [NODES];
__device__ int      g_ei   [2 * NEDGE];
__device__ int      g_deg  [NODES];
__device__ int      g_rowp [NODES];
__device__ int      g_pos  [NODES];
__device__ int      g_bsum [NSCAN];
__device__ int      g_boff [NSCAN];
__device__ int      g_srt  [AUGE];
__device__ int      g_is64;

// ------------------------- helpers ------------------------------------------
__device__ __forceinline__ float lrelu(float x) { return x >= 0.f ? x : 0.2f * x; }
__device__ __forceinline__ unsigned t32(float x) {
    unsigned r; asm("cvt.rna.tf32.f32 %0, %1;" : "=r"(r) : "f"(x)); return r;
}
__device__ __forceinline__ void mma_tf32(float4& d, const unsigned* a,
                                         unsigned b0, unsigned b1) {
    asm("mma.sync.aligned.m16n8k8.row.col.f32.tf32.tf32.f32 "
        "{%0,%1,%2,%3},{%4,%5,%6,%7},{%8,%9},{%0,%1,%2,%3};"
        : "+f"(d.x), "+f"(d.y), "+f"(d.z), "+f"(d.w)
        : "r"(a[0]), "r"(a[1]), "r"(a[2]), "r"(a[3]), "r"(b0), "r"(b1));
}

// ------------------------- edge index dtype detect + normalize --------------
__global__ void detect_k(const void* p) {
    __shared__ int nz;
    if (threadIdx.x == 0) nz = 0;
    __syncthreads();
    const int2* q = (const int2*)p;
    for (int i = threadIdx.x; i < 4096; i += blockDim.x)
        if (q[i].y != 0) nz = 1;
    __syncthreads();
    if (threadIdx.x == 0) g_is64 = (nz == 0) ? 1 : 0;
}
__global__ void conv_k(const void* p) {
    int i = blockIdx.x * blockDim.x + threadIdx.x;
    if (i >= 2 * NEDGE) return;
    long long v = g_is64 ? ((const long long*)p)[i]
                         : (long long)((const int*)p)[i];
    int vi = (int)v;
    g_ei[i] = vi;
    if (i >= NEDGE) atomicAdd(&g_deg[vi], 1);
}

// ------------------------- setup: seed degrees + repack Wm1 -----------------
__global__ void setup_k(const float* __restrict__ Wm1) {
    int i = blockIdx.x * blockDim.x + threadIdx.x;
    if (i < NODES) g_deg[i] = 1;
    if (i < HIDC * 2 * HIDC) {
        int k = i >> 7, j = i & 127;
        g_Bc[i] = (j < HIDC) ? Wm1[k * HIDC + j] : Wm1[(HIDC + k) * HIDC + (j - HIDC)];
    }
}

// ------------------------- hierarchical CSR scan -----------------------------
__global__ void __launch_bounds__(1024) scan1_k() {
    __shared__ int sh[1024];
    int t = threadIdx.x;
    int idx = blockIdx.x * 1024 + t;
    int v = (idx < NODES) ? g_deg[idx] : 0;
    sh[t] = v;
    __syncthreads();
    int acc = v;
    #pragma unroll
    for (int off = 1; off < 1024; off <<= 1) {
        int u = (t >= off) ? sh[t - off] : 0;
        __syncthreads();
        acc += u;
        sh[t] = acc;
        __syncthreads();
    }
    if (idx < NODES) g_rowp[idx] = acc - v;
    if (t == 1023) g_bsum[blockIdx.x] = acc;
}
__global__ void scan2_k() {
    int t = threadIdx.x;
    int v = (t < NSCAN) ? g_bsum[t] : 0;
    int x = v;
    #pragma unroll
    for (int off = 1; off < 64; off <<= 1) {
        int u = __shfl_up_sync(0xffffffffu, x, off, 32);
        if ((t & 31) >= off) x += u;
    }
    __shared__ int w0;
    if (t == 31) w0 = x;
    __syncthreads();
    if (t >= 32) x += w0;
    if (t < NSCAN) g_boff[t] = x - v;
}
__global__ void __launch_bounds__(1024) scan3_k() {
    int idx = blockIdx.x * 1024 + threadIdx.x;
    if (idx >= NODES) return;
    int r = g_rowp[idx] + g_boff[blockIdx.x];
    g_rowp[idx] = r;
    g_pos[idx]  = r;
}
__global__ void scatter_k() {
    int i = blockIdx.x * blockDim.x + threadIdx.x;
    if (i >= AUGE) return;
    int s, d;
    if (i < NEDGE) { s = g_ei[i]; d = g_ei[NEDGE + i]; } else { s = d = i - NEDGE; }
    int p = atomicAdd(&g_pos[d], 1);
    g_srt[p] = s;
}

// ---------------- tf32 tensor-core GEMM: 128x64 block, BK=32 ----------------
template<int AMODE, int CHALF>
__global__ void __launch_bounds__(256) gemmt_k(
    const float* __restrict__ A, const float* __restrict__ B,
    const float* __restrict__ biasA, const float* __restrict__ den,
    void* __restrict__ Cp, int M, int K, int Nc)
{
    __shared__ unsigned Asm[4 * 8 * 32 * 4];
    __shared__ unsigned Bsm[2 * 4 * 2 * 32 * 4];
    int t = threadIdx.x;
    int lane = t & 31, warp = t >> 5;
    int wm = warp >> 1, wn = warp & 1;
    int m0 = blockIdx.x * 128, n0 = blockIdx.y * 64;

    float4 acc[2][4];
    #pragma unroll
    for (int i = 0; i < 2; i++)
        #pragma unroll
        for (int j = 0; j < 4; j++) acc[i][j] = make_float4(0.f, 0.f, 0.f, 0.f);

    for (int k0 = 0; k0 < K; k0 += 32) {
        #pragma unroll
        for (int i = t; i < 1024; i += 256) {
            int r = i >> 3;
            int kq = (i & 7) << 2;
            int gr = m0 + r;
            float4 v = make_float4(0.f, 0.f, 0.f, 0.f);
            if (gr < M) {
                v = *(const float4*)(A + (long)gr * K + k0 + kq);
                if (AMODE == 1) {
                    float inv = 1.f / (den[gr * 4 + ((k0 + kq) >> 6)] + 1e-16f);
                    float4 b = *(const float4*)(biasA + k0 + kq);
                    v.x = fmaxf(v.x * inv + b.x, 0.f);
                    v.y = fmaxf(v.y * inv + b.y, 0.f);
                    v.z = fmaxf(v.z * inv + b.z, 0.f);
                    v.w = fmaxf(v.w * inv + b.w, 0.f);
                } else if (AMODE == 2) {
                    float inv = 1.f / (den[gr] + 1e-16f);
                    float4 b = *(const float4*)(biasA + k0 + kq);
                    v.x = v.x * inv + b.x; v.y = v.y * inv + b.y;
                    v.z = v.z * inv + b.z; v.w = v.w * inv + b.w;
                }
            }
            int kstep = kq >> 3;
            int mtile = r >> 4, rr = r & 15;
            int j = (rr >= 8 ? 1 : 0) + ((kq & 4) ? 2 : 0);
            int lane0 = (rr & 7) << 2;
            unsigned* bp = Asm + (((kstep * 8 + mtile) * 32) + lane0) * 4 + j;
            bp[(0 ^ kstep) * 4] = t32(v.x);
            bp[(1 ^ kstep) * 4] = t32(v.y);
            bp[(2 ^ kstep) * 4] = t32(v.z);
            bp[(3 ^ kstep) * 4] = t32(v.w);
        }
        #pragma unroll
        for (int i = t; i < 512; i += 256) {
            int kk = i >> 4;
            int nq = (i & 15) << 2;
            float4 v = *(const float4*)(B + (long)(k0 + kk) * Nc + n0 + nq);
            int kstep = kk >> 3, klo = kk & 3, bsel = ((kk & 7) >= 4);
            unsigned tv[4] = { t32(v.x), t32(v.y), t32(v.z), t32(v.w) };
            #pragma unroll
            for (int c = 0; c < 4; c++) {
                int ng = nq + c;
                int g = ng >> 5, nn = ng & 31, tt = nn >> 3;
                int ln = ((nn & 7) << 2) | klo;
                Bsm[(tt >> 1) * 1024 + (((kstep * 2 + g) * 32) + ln) * 4
                    + (tt & 1) * 2 + bsel] = tv[c];
            }
        }
        __syncthreads();
        #pragma unroll
        for (int kstep = 0; kstep < 4; kstep++) {
            unsigned a[2][4], b[8];
            #pragma unroll
            for (int i = 0; i < 2; i++)
                *(uint4*)a[i] = *(const uint4*)
                    &Asm[(((kstep * 8) + (wm * 2 + i)) * 32 + (lane ^ kstep)) * 4];
            *(uint4*)&b[0] = *(const uint4*)&Bsm[(((kstep * 2 + wn) * 32) + lane) * 4];
            *(uint4*)&b[4] = *(const uint4*)&Bsm[1024 + (((kstep * 2 + wn) * 32) + lane) * 4];
            #pragma unroll
            for (int i = 0; i < 2; i++) {
                mma_tf32(acc[i][0], a[i], b[0], b[1]);
                mma_tf32(acc[i][1], a[i], b[2], b[3]);
                mma_tf32(acc[i][2], a[i], b[4], b[5]);
                mma_tf32(acc[i][3], a[i], b[6], b[7]);
            }
        }
        __syncthreads();
    }
    int mw = m0 + wm * 32;
    int nw = n0 + wn * 32;
    #pragma unroll
    for (int i = 0; i < 2; i++) {
        int rlo = mw + i * 16 + (lane >> 2);
        int rhi = rlo + 8;
        #pragma unroll
        for (int tt = 0; tt < 4; tt++) {
            int col = nw + tt * 8 + (lane & 3) * 2;
            if (CHALF) {
                __half* C = (__half*)Cp;
                if (rlo < M)
                    *(__half2*)(C + (long)rlo * Nc + col) =
                        __floats2half2_rn(acc[i][tt].x, acc[i][tt].y);
                if (rhi < M)
                    *(__half2*)(C + (long)rhi * Nc + col) =
                        __floats2half2_rn(acc[i][tt].z, acc[i][tt].w);
            } else {
                float* C = (float*)Cp;
                if (rlo < M)
                    *(float2*)(C + (long)rlo * Nc + col) = make_float2(acc[i][tt].x, acc[i][tt].y);
                if (rhi < M)
                    *(float2*)(C + (long)rhi * Nc + col) = make_float2(acc[i][tt].z, acc[i][tt].w);
            }
        }
    }
}

// ------------------------- layer-1 scores: warp per node (fp16 rows) --------
__global__ void scores1_k(const float* __restrict__ asrc,
                          const float* __restrict__ adst,
                          float* __restrict__ ssrc, float* __restrict__ sdst)
{
    int w = (int)(((long)blockIdx.x * blockDim.x + threadIdx.x) >> 5);
    if (w >= NODES) return;
    int lane = threadIdx.x & 31;
    uint4 u = *(const uint4*)(g_h1h + (long)w * 256 + lane * 8);
    float2 f0 = __half22float2(*(__half2*)&u.x);
    float2 f1 = __half22float2(*(__half2*)&u.y);
    float2 f2 = __half22float2(*(__half2*)&u.z);
    float2 f3 = __half22float2(*(__half2*)&u.w);
    int head = lane >> 3;
    int cbase = head * 64 + ((lane * 8) & 63);
    float4 a0 = *(const float4*)(asrc + cbase);
    float4 a1 = *(const float4*)(asrc + cbase + 4);
    float4 d0 = *(const float4*)(adst + cbase);
    float4 d1 = *(const float4*)(adst + cbase + 4);
    float ss = f0.x*a0.x + f0.y*a0.y + f1.x*a0.z + f1.y*a0.w
             + f2.x*a1.x + f2.y*a1.y + f3.x*a1.z + f3.y*a1.w;
    float sd = f0.x*d0.x + f0.y*d0.y + f1.x*d0.z + f1.y*d0.w
             + f2.x*d1.x + f2.y*d1.y + f3.x*d1.z + f3.y*d1.w;
    #pragma unroll
    for (int o = 4; o; o >>= 1) {
        ss += __shfl_xor_sync(0xffffffffu, ss, o);
        sd += __shfl_xor_sync(0xffffffffu, sd, o);
    }
    if ((lane & 7) == 0) {
        ssrc[w * 4 + head] = ss;
        sdst[w * 4 + head] = sd;
    }
}

// ------------------------- layer-2 scores: warp per node, 1 head ------------
__global__ void scores2_k(const float* __restrict__ h,
                          const float* __restrict__ asrc,
                          const float* __restrict__ adst,
                          float* __restrict__ ssrc, float* __restrict__ sdst)
{
    int w = (int)(((long)blockIdx.x * blockDim.x + threadIdx.x) >> 5);
    if (w >= NODES) return;
    int lane = threadIdx.x & 31;
    const float* row = h + (long)w * 64;
    float v1 = row[lane], v2 = row[lane + 32];
    float ss = v1 * asrc[lane] + v2 * asrc[lane + 32];
    float sd = v1 * adst[lane] + v2 * adst[lane + 32];
    #pragma unroll
    for (int o = 16; o; o >>= 1) {
        ss += __shfl_xor_sync(0xffffffffu, ss, o);
        sd += __shfl_xor_sync(0xffffffffu, sd, o);
    }
    if (lane == 0) { ssrc[w] = ss; sdst[w] = sd; }
}

// -------- layer-1 CSR aggregation: warp per dst node, unroll-2 --------------
__global__ void __launch_bounds__(256) eagg1c_k() {
    int node = (int)(((long)blockIdx.x * blockDim.x + threadIdx.x) >> 5);
    if (node >= NODES) return;
    int lane = threadIdx.x & 31;
    int start = g_rowp[node], deg = g_deg[node];
    float sdv = (lane < 4) ? g_sdst1[node * 4 + lane] : 0.f;
    int head = lane >> 3;
    float acc[8] = {};
    float den = 0.f;
    int e = 0;
    for (; e + 2 <= deg; e += 2) {
        int s0 = g_srt[start + e];
        int s1 = g_srt[start + e + 1];
        float ex0 = 0.f, ex1 = 0.f;
        if (lane < 4) {
            ex0 = __expf(lrelu(g_ssrc1[s0 * 4 + lane] + sdv));
            ex1 = __expf(lrelu(g_ssrc1[s1 * 4 + lane] + sdv));
            den += ex0 + ex1;
        }
        float exa = __shfl_sync(0xffffffffu, ex0, head);
        float exb = __shfl_sync(0xffffffffu, ex1, head);
        uint4 u0 = *(const uint4*)(g_h1h + (long)s0 * 256 + lane * 8);
        uint4 u1 = *(const uint4*)(g_h1h + (long)s1 * 256 + lane * 8);
        float2 a0 = __half22float2(*(__half2*)&u0.x);
        float2 a1 = __half22float2(*(__half2*)&u0.y);
        float2 a2 = __half22float2(*(__half2*)&u0.z);
        float2 a3 = __half22float2(*(__half2*)&u0.w);
        float2 b0 = __half22float2(*(__half2*)&u1.x);
        float2 b1 = __half22float2(*(__half2*)&u1.y);
        float2 b2 = __half22float2(*(__half2*)&u1.z);
        float2 b3 = __half22float2(*(__half2*)&u1.w);
        acc[0] += a0.x * exa + b0.x * exb; acc[1] += a0.y * exa + b0.y * exb;
        acc[2] += a1.x * exa + b1.x * exb; acc[3] += a1.y * exa + b1.y * exb;
        acc[4] += a2.x * exa + b2.x * exb; acc[5] += a2.y * exa + b2.y * exb;
        acc[6] += a3.x * exa + b3.x * exb; acc[7] += a3.y * exa + b3.y * exb;
    }
    if (e < deg) {
        int s0 = g_srt[start + e];
        float ex0 = 0.f;
        if (lane < 4) {
            ex0 = __expf(lrelu(g_ssrc1[s0 * 4 + lane] + sdv));
            den += ex0;
        }
        float exa = __shfl_sync(0xffffffffu, ex0, head);
        uint4 u0 = *(const uint4*)(g_h1h + (long)s0 * 256 + lane * 8);
        float2 a0 = __half22float2(*(__half2*)&u0.x);
        float2 a1 = __half22float2(*(__half2*)&u0.y);
        float2 a2 = __half22float2(*(__half2*)&u0.z);
        float2 a3 = __half22float2(*(__half2*)&u0.w);
        acc[0] += a0.x * exa; acc[1] += a0.y * exa;
        acc[2] += a1.x * exa; acc[3] += a1.y * exa;
        acc[4] += a2.x * exa; acc[5] += a2.y * exa;
        acc[6] += a3.x * exa; acc[7] += a3.y * exa;
    }
    float* ap = g_agg1 + (long)node * H1DIM + lane * 8;
    *(float4*)ap       = make_float4(acc[0], acc[1], acc[2], acc[3]);
    *(float4*)(ap + 4) = make_float4(acc[4], acc[5], acc[6], acc[7]);
    if (lane < 4) g_den1[node * 4 + lane] = den;
}

// -------- layer-2 CSR aggregation: warp per dst node, unroll-2 ---------------
__global__ void __launch_bounds__(256) eagg2c_k() {
    int node = (int)(((long)blockIdx.x * blockDim.x + threadIdx.x) >> 5);
    if (node >= NODES) return;
    int lane = threadIdx.x & 31;
    int start = g_rowp[node], deg = g_deg[node];
    float sdv = (lane == 0) ? g_sdst2[node] : 0.f;
    float a0 = 0.f, a1 = 0.f, den = 0.f;
    int e = 0;
    for (; e + 2 <= deg; e += 2) {
        int s0 = g_srt[start + e];
        int s1 = g_srt[start + e + 1];
        float ex0 = 0.f, ex1 = 0.f;
        if (lane == 0) {
            ex0 = __expf(lrelu(g_ssrc2[s0] + sdv));
            ex1 = __expf(lrelu(g_ssrc2[s1] + sdv));
            den += ex0 + ex1;
        }
        ex0 = __shfl_sync(0xffffffffu, ex0, 0);
        ex1 = __shfl_sync(0xffffffffu, ex1, 0);
        float2 v0 = ((const float2*)(g_h2lin + (long)s0 * HIDC))[lane];
        float2 v1 = ((const float2*)(g_h2lin + (long)s1 * HIDC))[lane];
        a0 += v0.x * ex0 + v1.x * ex1;
        a1 += v0.y * ex0 + v1.y * ex1;
    }
    if (e < deg) {
        int s0 = g_srt[start + e];
        float ex0 = 0.f;
        if (lane == 0) {
            ex0 = __expf(lrelu(g_ssrc2[s0] + sdv));
            den += ex0;
        }
        ex0 = __shfl_sync(0xffffffffu, ex0, 0);
        float2 v0 = ((const float2*)(g_h2lin + (long)s0 * HIDC))[lane];
        a0 += v0.x * ex0;
        a1 += v0.y * ex0;
    }
    ((float2*)(g_agg2 + (long)node * HIDC))[lane] = make_float2(a0, a1);
    if (lane == 0) g_den2[node] = den;
}

// ------------------- per-edge MLP finish: 2 edges per warp ------------------
__global__ void __launch_bounds__(256) edge_k(
    const float* __restrict__ bm1, const float* __restrict__ Wm2,
    const float* __restrict__ bm2, float* __restrict__ out)
{
    long tid = (long)blockIdx.x * blockDim.x + threadIdx.x;
    int warp = (int)(tid >> 5);
    int lane = threadIdx.x & 31;
    int sub = lane >> 4;           // half-warp: 0 or 1
    int l = lane & 15;             // lane within half-warp: 4 cols each
    int w = warp * 2 + sub;        // edge id
    if (w >= NEDGE) return;
    int s = g_ei[w], d = g_ei[NEDGE + w];
    // lane owns cols 4l..4l+3 (8-byte aligned fp16 loads)
    float2 p01, p23, q01, q23;
    {
        uint2 up = *(const uint2*)(g_PQh + (long)s * 128 + l * 4);
        uint2 uq = *(const uint2*)(g_PQh + (long)d * 128 + 64 + l * 4);
        p01 = __half22float2(*(__half2*)&up.x);
        p23 = __half22float2(*(__half2*)&up.y);
        q01 = __half22float2(*(__half2*)&uq.x);
        q23 = __half22float2(*(__half2*)&uq.y);
    }
    float4 b = *(const float4*)(bm1 + l * 4);
    float4 wA = *(const float4*)(Wm2 + l * 8);       // rows 4l,4l+1 (2 outs each)
    float4 wB = *(const float4*)(Wm2 + l * 8 + 4);   // rows 4l+2,4l+3
    float h0 = fmaxf(p01.x + q01.x + b.x, 0.f);
    float h1 = fmaxf(p01.y + q01.y + b.y, 0.f);
    float h2 = fmaxf(p23.x + q23.x + b.z, 0.f);
    float h3 = fmaxf(p23.y + q23.y + b.w, 0.f);
    float o0 = h0 * wA.x + h1 * wA.z + h2 * wB.x + h3 * wB.z;
    float o1 = h0 * wA.y + h1 * wA.w + h2 * wB.y + h3 * wB.w;
    #pragma unroll
    for (int off = 8; off; off >>= 1) {
        o0 += __shfl_xor_sync(0xffffffffu, o0, off);
        o1 += __shfl_xor_sync(0xffffffffu, o1, off);
    }
    if (l == 0) {
        float2 r = make_float2(o0 + bm2[0], o1 + bm2[1]);
        *(float2*)(out + (long)w * 2) = r;
    }
}

// ------------------------- launch -------------------------------------------
extern "C" void kernel_launch(void* const* d_in, const int* in_sizes, int n_in,
                              void* d_out, int out_size)
{
    const float* x   = (const float*)d_in[0];
    const void*  eir = d_in[1];
    const float* W1  = (const float*)d_in[2];
    const float* as1 = (const float*)d_in[3];
    const float* ad1 = (const float*)d_in[4];
    const float* b1  = (const float*)d_in[5];
    const float* W2  = (const float*)d_in[6];
    const float* as2 = (const float*)d_in[7];
    const float* ad2 = (const float*)d_in[8];
    const float* b2  = (const float*)d_in[9];
    const float* Wm1 = (const float*)d_in[10];
    const float* bm1 = (const float*)d_in[11];
    const float* Wm2 = (const float*)d_in[12];
    const float* bm2 = (const float*)d_in[13];
    float* out = (float*)d_out;

    void* p;
    cudaGetSymbolAddress(&p, g_h1h);   void*  h1h   = p;
    cudaGetSymbolAddress(&p, g_agg1);  float* agg1  = (float*)p;
    cudaGetSymbolAddress(&p, g_h2lin); float* h2lin = (float*)p;
    cudaGetSymbolAddress(&p, g_agg2);  float* agg2  = (float*)p;
    cudaGetSymbolAddress(&p, g_PQh);   void*  PQh   = p;
    cudaGetSymbolAddress(&p, g_Bc);    float* Bc    = (float*)p;
    cudaGetSymbolAddress(&p, g_ssrc1); float* ssrc1 = (float*)p;
    cudaGetSymbolAddress(&p, g_sdst1); float* sdst1 = (float*)p;
    cudaGetSymbolAddress(&p, g_den1);  float* den1  = (float*)p;
    cudaGetSymbolAddress(&p, g_ssrc2); float* ssrc2 = (float*)p;
    cudaGetSymbolAddress(&p, g_sdst2); float* sdst2 = (float*)p;
    cudaGetSymbolAddress(&p, g_den2);  float* den2  = (float*)p;

    const int MT = (NODES + 127) / 128;   // 391

    detect_k<<<1, 256>>>(eir);
    setup_k<<<(NODES + 255) / 256, 256>>>(Wm1);
    conv_k<<<(2 * NEDGE + 255) / 256, 256>>>(eir);
    scan1_k<<<NSCAN, 1024>>>();
    scan2_k<<<1, 64>>>();
    scan3_k<<<NSCAN, 1024>>>();
    scatter_k<<<(AUGE + 255) / 256, 256>>>();

    // ---- layer 1 (4 heads, concat); C stored fp16 ----
    gemmt_k<0, 1><<<dim3(MT, H1DIM / 64), 256>>>(
        x, W1, nullptr, nullptr, h1h, NODES, INC, H1DIM);
    scores1_k<<<(NODES * 32 + 255) / 256, 256>>>(as1, ad1, ssrc1, sdst1);
    eagg1c_k<<<(NODES * 32 + 255) / 256, 256>>>();

    // ---- layer 2; relu(agg1/den1 + b1) fused into A-load ----
    gemmt_k<1, 0><<<dim3(MT, 1), 256>>>(
        agg1, W2, b1, den1, h2lin, NODES, H1DIM, HIDC);
    scores2_k<<<(NODES * 32 + 255) / 256, 256>>>(h2lin, as2, ad2, ssrc2, sdst2);
    eagg2c_k<<<(NODES * 32 + 255) / 256, 256>>>();

    // ---- edge MLP, factorized; PQ stored fp16 ----
    gemmt_k<2, 1><<<dim3(MT, 2), 256>>>(
        agg2, Bc, b2, den2, PQh, NODES, HIDC, 2 * HIDC);
    edge_k<<<(int)(((long)NEDGE / 2 * 32 + 255) / 256), 256>>>(bm1, Wm2, bm2, out);
}